// round 10
// baseline (speedup 1.0000x reference)
#include <cuda_runtime.h>
#include <cuda_bf16.h>
#include <cstdint>

#define B_ 16
#define T_ 4096
#define D_ 1024
#define C_ 128
#define M_ (B_*T_)        // 65536 tokens
#define GROUPS 16         // row-groups for recurrence parallelism (8 rows each)
#define LCH 4             // chunk length inside recurrence
#define NCH (T_/LCH)      // 1024 chunks per sequence

typedef __nv_bfloat16 bf16;

// ---------------- scratch (static device globals; no allocation) -------------
__device__ float g_q[(size_t)M_*C_];
__device__ float g_k[(size_t)M_*C_];
__device__ float g_v[(size_t)M_*C_];
__device__ float g_g[(size_t)M_*C_];
__device__ float g_qT[(size_t)M_*C_];   // [B][C][T]
__device__ float g_vT[(size_t)M_*C_];   // [B][C][T]
__device__ float g_a[M_];
__device__ float g_b[M_];
__device__ float g_opart[(size_t)GROUPS*M_*C_];
__device__ float g_gram[(size_t)B_*NCH*8];

__device__ bf16 g_xh[(size_t)M_*D_];
__device__ bf16 g_xl[(size_t)M_*D_];
__device__ bf16 g_oh[(size_t)M_*C_];
__device__ bf16 g_ol[(size_t)M_*C_];
__device__ bf16 g_wqh[C_*D_], g_wql[C_*D_];
__device__ bf16 g_wkh[C_*D_], g_wkl[C_*D_];
__device__ bf16 g_wvh[C_*D_], g_wvl[C_*D_];
__device__ bf16 g_wgh[C_*D_], g_wgl[C_*D_];
__device__ bf16 g_woh[D_*C_], g_wol[D_*C_];

__device__ __forceinline__ float sigmoidf_(float x) { return 1.0f / (1.0f + expf(-x)); }

// =============================================================================
// fused_prep: blocks [0, M_/8)            -> alpha/beta + x hi/lo split
//             blocks [M_/8, M_/8 + 640)   -> weight hi/lo splits (5 matrices)
// =============================================================================
__global__ __launch_bounds__(256) void fused_prep(
    const float* __restrict__ x,
    const float* __restrict__ Wa, const float* __restrict__ ba,
    const float* __restrict__ Wb, const float* __restrict__ bb,
    float* __restrict__ a_out, float* __restrict__ b_out,
    bf16* __restrict__ xh, bf16* __restrict__ xl,
    const float* Wq, const float* Wk, const float* Wv, const float* Wg, const float* Wo,
    bf16* wqh, bf16* wql, bf16* wkh, bf16* wkl, bf16* wvh, bf16* wvl,
    bf16* wgh, bf16* wgl, bf16* woh, bf16* wol)
{
    const int tid = threadIdx.x;
    constexpr int NAB = M_/8;

    if (blockIdx.x >= NAB) {
        const int widx = blockIdx.x - NAB;
        const int mat  = widx >> 7;
        const float* in; bf16 *hi, *lo;
        if      (mat == 0) { in = Wq; hi = wqh; lo = wql; }
        else if (mat == 1) { in = Wk; hi = wkh; lo = wkl; }
        else if (mat == 2) { in = Wv; hi = wvh; lo = wvl; }
        else if (mat == 3) { in = Wg; hi = wgh; lo = wgl; }
        else               { in = Wo; hi = woh; lo = wol; }
        const int i = (widx & 127) * 256 + tid;
        float4 xv = *(const float4*)(in + (size_t)i * 4);
        bf16 h0 = __float2bfloat16_rn(xv.x);
        bf16 h1 = __float2bfloat16_rn(xv.y);
        bf16 h2 = __float2bfloat16_rn(xv.z);
        bf16 h3 = __float2bfloat16_rn(xv.w);
        bf16 l0 = __float2bfloat16_rn(xv.x - __bfloat162float(h0));
        bf16 l1 = __float2bfloat16_rn(xv.y - __bfloat162float(h1));
        bf16 l2 = __float2bfloat16_rn(xv.z - __bfloat162float(h2));
        bf16 l3 = __float2bfloat16_rn(xv.w - __bfloat162float(h3));
        __nv_bfloat162* H = (__nv_bfloat162*)(hi + (size_t)i * 4);
        __nv_bfloat162* L = (__nv_bfloat162*)(lo + (size_t)i * 4);
        H[0] = __nv_bfloat162(h0, h1); H[1] = __nv_bfloat162(h2, h3);
        L[0] = __nv_bfloat162(l0, l1); L[1] = __nv_bfloat162(l2, l3);
        return;
    }

    __shared__ __align__(16) float sWa[D_];
    __shared__ __align__(16) float sWb[D_];
    for (int i = tid; i < D_; i += 256) { sWa[i] = Wa[i]; sWb[i] = Wb[i]; }
    __syncthreads();

    const int warp = tid >> 5, lane = tid & 31;
    const int tok  = blockIdx.x * 8 + warp;
    const size_t base = (size_t)tok * D_;
    const float* xr = x + base;

    float da = 0.0f, db = 0.0f;
#pragma unroll
    for (int j = 0; j < 8; ++j) {
        const int off = j*128 + lane*4;
        float4 xv = *(const float4*)(xr  + off);
        float4 wa = *(const float4*)(sWa + off);
        float4 wb = *(const float4*)(sWb + off);
        da += xv.x*wa.x + xv.y*wa.y + xv.z*wa.z + xv.w*wa.w;
        db += xv.x*wb.x + xv.y*wb.y + xv.z*wb.z + xv.w*wb.w;

        bf16 h0 = __float2bfloat16_rn(xv.x);
        bf16 h1 = __float2bfloat16_rn(xv.y);
        bf16 h2 = __float2bfloat16_rn(xv.z);
        bf16 h3 = __float2bfloat16_rn(xv.w);
        bf16 l0 = __float2bfloat16_rn(xv.x - __bfloat162float(h0));
        bf16 l1 = __float2bfloat16_rn(xv.y - __bfloat162float(h1));
        bf16 l2 = __float2bfloat16_rn(xv.z - __bfloat162float(h2));
        bf16 l3 = __float2bfloat16_rn(xv.w - __bfloat162float(h3));
        __nv_bfloat162* H = (__nv_bfloat162*)(xh + base + off);
        __nv_bfloat162* L = (__nv_bfloat162*)(xl + base + off);
        H[0] = __nv_bfloat162(h0, h1); H[1] = __nv_bfloat162(h2, h3);
        L[0] = __nv_bfloat162(l0, l1); L[1] = __nv_bfloat162(l2, l3);
    }
#pragma unroll
    for (int off = 16; off > 0; off >>= 1) {
        da += __shfl_xor_sync(0xffffffffu, da, off);
        db += __shfl_xor_sync(0xffffffffu, db, off);
    }
    if (lane == 0) {
        a_out[tok] = sigmoidf_(da + ba[0]);
        b_out[tok] = sigmoidf_(db + bb[0]);
    }
}

// =============================================================================
// Tensor-core NT GEMM core (HMMA mma.sync).
// =============================================================================
__device__ __forceinline__ void ldsm4(uint32_t& r0, uint32_t& r1,
                                      uint32_t& r2, uint32_t& r3, uint32_t a)
{
    asm volatile("ldmatrix.sync.aligned.m8n8.x4.shared.b16 {%0,%1,%2,%3}, [%4];"
                 : "=r"(r0), "=r"(r1), "=r"(r2), "=r"(r3) : "r"(a));
}

__device__ __forceinline__ void mma16816(float c[4], const uint32_t a[4], const uint32_t b[2])
{
    asm volatile("mma.sync.aligned.m16n8k16.row.col.f32.bf16.bf16.f32 "
                 "{%0,%1,%2,%3}, {%4,%5,%6,%7}, {%8,%9}, {%0,%1,%2,%3};"
                 : "+f"(c[0]), "+f"(c[1]), "+f"(c[2]), "+f"(c[3])
                 : "r"(a[0]), "r"(a[1]), "r"(a[2]), "r"(a[3]), "r"(b[0]), "r"(b[1]));
}

template<int KDIM>
__device__ __forceinline__ void mma_loop(const bf16* __restrict__ A0,
                                         const bf16* __restrict__ A1,
                                         const bf16* __restrict__ A2,
                                         const bf16* __restrict__ B0,
                                         const bf16* __restrict__ B1,
                                         const bf16* __restrict__ B2,
                                         int m0, uint4* sA, uint4* sB,
                                         float acc[4][4][4])
{
    constexpr int KIT = KDIM / 32;
    constexpr int TOT = 3 * KIT;
    const int tid  = threadIdx.x;
    const int lane = tid & 31, warp = tid >> 5;
    const int wm = warp & 1, wn = warp >> 1;

    const int r0_ = tid >> 2,        u_ = tid & 3;
    const int r1_ = 64 + (tid >> 2);
    const int st0 = r0_ * 4 + (u_ ^ ((r0_ >> 1) & 3));
    const int st1 = r1_ * 4 + (u_ ^ ((r1_ >> 1) & 3));

    const uint32_t saB = (uint32_t)__cvta_generic_to_shared(sA);
    const uint32_t sbB = (uint32_t)__cvta_generic_to_shared(sB);

    uint4 ra0, ra1, rb0, rb1;
    {
        ra0 = *(const uint4*)(A0 + (size_t)(m0 + r0_) * KDIM + u_ * 8);
        ra1 = *(const uint4*)(A0 + (size_t)(m0 + r1_) * KDIM + u_ * 8);
        rb0 = *(const uint4*)(B0 + (size_t)r0_ * KDIM + u_ * 8);
        rb1 = *(const uint4*)(B0 + (size_t)r1_ * KDIM + u_ * 8);
    }

#pragma unroll 1
    for (int it = 0; it < TOT; ++it) {
        const int buf = it & 1;
        sA[buf * 512 + st0] = ra0; sA[buf * 512 + st1] = ra1;
        sB[buf * 512 + st0] = rb0; sB[buf * 512 + st1] = rb1;
        __syncthreads();

        if (it + 1 < TOT) {
            const int nit = it + 1;
            const int p = nit / KIT;
            const int kk = (nit - p * KIT) * 32;
            const bf16* Ap = (p == 0) ? A0 : (p == 1) ? A1 : A2;
            const bf16* Bp = (p == 0) ? B0 : (p == 1) ? B1 : B2;
            ra0 = *(const uint4*)(Ap + (size_t)(m0 + r0_) * KDIM + kk + u_ * 8);
            ra1 = *(const uint4*)(Ap + (size_t)(m0 + r1_) * KDIM + kk + u_ * 8);
            rb0 = *(const uint4*)(Bp + (size_t)r0_ * KDIM + kk + u_ * 8);
            rb1 = *(const uint4*)(Bp + (size_t)r1_ * KDIM + kk + u_ * 8);
        }

        const uint32_t aBase = saB + buf * 8192;
        const uint32_t bBase = sbB + buf * 8192;
#pragma unroll
        for (int ks = 0; ks < 2; ++ks) {
            uint32_t af[4][4], bfr[4][2];
#pragma unroll
            for (int mt = 0; mt < 4; ++mt) {
                const int row = wm * 64 + mt * 16 + (lane & 15);
                const int u = ks * 2 + (lane >> 4);
                ldsm4(af[mt][0], af[mt][1], af[mt][2], af[mt][3],
                      aBase + (uint32_t)((row * 4 + (u ^ ((row >> 1) & 3))) * 16));
            }
#pragma unroll
            for (int j = 0; j < 2; ++j) {
                const int gq = lane >> 3;
                const int n = wn * 32 + j * 16 + ((gq >> 1) << 3) + (lane & 7);
                const int u = ks * 2 + (gq & 1);
                uint32_t t0, t1, t2, t3;
                ldsm4(t0, t1, t2, t3,
                      bBase + (uint32_t)((n * 4 + (u ^ ((n >> 1) & 3))) * 16));
                bfr[j*2][0] = t0; bfr[j*2][1] = t1;
                bfr[j*2+1][0] = t2; bfr[j*2+1][1] = t3;
            }
#pragma unroll
            for (int mt = 0; mt < 4; ++mt)
#pragma unroll
                for (int nt = 0; nt < 4; ++nt)
                    mma16816(acc[mt][nt], af[mt], bfr[nt]);
        }
    }
}

// =============================================================================
// Fused 4-projection GEMM (HMMA).
// =============================================================================
__global__ __launch_bounds__(256, 2) void proj_gemm(
    const bf16* __restrict__ xh, const bf16* __restrict__ xl,
    const bf16* wqh, const bf16* wql, const bf16* wkh, const bf16* wkl,
    const bf16* wvh, const bf16* wvl, const bf16* wgh, const bf16* wgl,
    const float* bq, const float* bk, const float* bv, const float* bg,
    float* outq, float* outk, float* outv, float* outg)
{
    __shared__ uint4 sA[1024];
    __shared__ uint4 sB[1024];
    __shared__ float snorm[4][128];

    const int proj = blockIdx.x;
    const int m0 = blockIdx.y * 128;
    const bf16 *Bh, *Bl; const float* bias; float* C;
    if      (proj == 0) { Bh = wqh; Bl = wql; bias = bq; C = outq; }
    else if (proj == 1) { Bh = wkh; Bl = wkl; bias = bk; C = outk; }
    else if (proj == 2) { Bh = wvh; Bl = wvl; bias = bv; C = outv; }
    else                { Bh = wgh; Bl = wgl; bias = bg; C = outg; }

    float acc[4][4][4];
#pragma unroll
    for (int mt = 0; mt < 4; ++mt)
#pragma unroll
        for (int nt = 0; nt < 4; ++nt)
#pragma unroll
            for (int c = 0; c < 4; ++c) acc[mt][nt][c] = 0.0f;

    mma_loop<D_>(xh, xh, xl, Bh, Bl, Bh, m0, sA, sB, acc);

    const int lane = threadIdx.x & 31, warp = threadIdx.x >> 5;
    const int wm = warp & 1, wn = warp >> 1;

#pragma unroll
    for (int nt = 0; nt < 4; ++nt) {
        const int col = wn * 32 + nt * 8 + (lane & 3) * 2;
        const float b0 = bias[col], b1 = bias[col + 1];
#pragma unroll
        for (int mt = 0; mt < 4; ++mt) {
            acc[mt][nt][0] += b0; acc[mt][nt][1] += b1;
            acc[mt][nt][2] += b0; acc[mt][nt][3] += b1;
        }
    }

    if (proj == 3) {
#pragma unroll
        for (int mt = 0; mt < 4; ++mt)
#pragma unroll
            for (int nt = 0; nt < 4; ++nt)
#pragma unroll
                for (int c = 0; c < 4; ++c)
                    acc[mt][nt][c] = sigmoidf_(acc[mt][nt][c]);
    }

    if (proj == 1) {
#pragma unroll
        for (int mt = 0; mt < 4; ++mt)
#pragma unroll
            for (int h = 0; h < 2; ++h) {
                float ss = 0.0f;
#pragma unroll
                for (int nt = 0; nt < 4; ++nt) {
                    ss += acc[mt][nt][2*h] * acc[mt][nt][2*h];
                    ss += acc[mt][nt][2*h+1] * acc[mt][nt][2*h+1];
                }
                ss += __shfl_xor_sync(0xffffffffu, ss, 1);
                ss += __shfl_xor_sync(0xffffffffu, ss, 2);
                if ((lane & 3) == 0)
                    snorm[wn][wm*64 + mt*16 + h*8 + (lane >> 2)] = ss;
            }
        __syncthreads();
#pragma unroll
        for (int mt = 0; mt < 4; ++mt)
#pragma unroll
            for (int h = 0; h < 2; ++h) {
                const int row = wm*64 + mt*16 + h*8 + (lane >> 2);
                const float s = snorm[0][row] + snorm[1][row] + snorm[2][row] + snorm[3][row];
                const float inv = 1.0f / fmaxf(sqrtf(s), 1e-12f);
#pragma unroll
                for (int nt = 0; nt < 4; ++nt) {
                    acc[mt][nt][2*h]   *= inv;
                    acc[mt][nt][2*h+1] *= inv;
                }
            }
    }

#pragma unroll
    for (int mt = 0; mt < 4; ++mt) {
        const int r = m0 + wm*64 + mt*16 + (lane >> 2);
#pragma unroll
        for (int nt = 0; nt < 4; ++nt) {
            const int col = wn*32 + nt*8 + (lane & 3)*2;
            *(float2*)(C + (size_t)r * C_ + col)       = make_float2(acc[mt][nt][0], acc[mt][nt][1]);
            *(float2*)(C + (size_t)(r+8) * C_ + col)   = make_float2(acc[mt][nt][2], acc[mt][nt][3]);
        }
    }
}

// =============================================================================
// Output GEMM (HMMA).
// =============================================================================
__global__ __launch_bounds__(256, 2) void out_gemm(
    const bf16* __restrict__ oh, const bf16* __restrict__ ol,
    const bf16* __restrict__ woh, const bf16* __restrict__ wol,
    const float* __restrict__ bo, float* __restrict__ out)
{
    __shared__ uint4 sA[1024];
    __shared__ uint4 sB[1024];

    const int n0 = blockIdx.x * 128;
    const int m0 = blockIdx.y * 128;
    const bf16* Bh = woh + (size_t)n0 * C_;
    const bf16* Bl = wol + (size_t)n0 * C_;

    float acc[4][4][4];
#pragma unroll
    for (int mt = 0; mt < 4; ++mt)
#pragma unroll
        for (int nt = 0; nt < 4; ++nt)
#pragma unroll
            for (int c = 0; c < 4; ++c) acc[mt][nt][c] = 0.0f;

    mma_loop<C_>(oh, oh, ol, Bh, Bl, Bh, m0, sA, sB, acc);

    const int lane = threadIdx.x & 31, warp = threadIdx.x >> 5;
    const int wm = warp & 1, wn = warp >> 1;

#pragma unroll
    for (int mt = 0; mt < 4; ++mt) {
        const int r = m0 + wm*64 + mt*16 + (lane >> 2);
#pragma unroll
        for (int nt = 0; nt < 4; ++nt) {
            const int col = n0 + wn*32 + nt*8 + (lane & 3)*2;
            const float b0 = bo[col], b1 = bo[col + 1];
            *(float2*)(out + (size_t)r * D_ + col)
                = make_float2(acc[mt][nt][0] + b0, acc[mt][nt][1] + b1);
            *(float2*)(out + (size_t)(r+8) * D_ + col)
                = make_float2(acc[mt][nt][2] + b0, acc[mt][nt][3] + b1);
        }
    }
}

// =============================================================================
// prep2: blocks [0, 2048)        -> chunk Gram precompute (1 warp per chunk)
//        blocks [2048, 2048+16384) -> q/v transpose to [B][C][T]
// =============================================================================
__global__ __launch_bounds__(256) void prep2(const float* __restrict__ k,
                                             const float* __restrict__ q,
                                             const float* __restrict__ v,
                                             float* __restrict__ gram,
                                             float* __restrict__ qT,
                                             float* __restrict__ vT)
{
    const int tid = threadIdx.x;

    if (blockIdx.x < 2048) {
        // ---- Gram ----
        const int warp = tid >> 5, lane = tid & 31;
        const int cid = blockIdx.x * 8 + warp;      // 0 .. B_*NCH-1
        const int bb = cid >> 10, tc = cid & 1023;
        const float* kg = k + ((size_t)bb * T_ + (size_t)tc * LCH) * C_ + lane * 4;

        float4 k0 = *(const float4*)(kg + 0*C_);
        float4 k1 = *(const float4*)(kg + 1*C_);
        float4 k2 = *(const float4*)(kg + 2*C_);
        float4 k3 = *(const float4*)(kg + 3*C_);

        float G01 = k0.x*k1.x + k0.y*k1.y + k0.z*k1.z + k0.w*k1.w;
        float G02 = k0.x*k2.x + k0.y*k2.y + k0.z*k2.z + k0.w*k2.w;
        float G03 = k0.x*k3.x + k0.y*k3.y + k0.z*k3.z + k0.w*k3.w;
        float G12 = k1.x*k2.x + k1.y*k2.y + k1.z*k2.z + k1.w*k2.w;
        float G13 = k1.x*k3.x + k1.y*k3.y + k1.z*k3.z + k1.w*k3.w;
        float G23 = k2.x*k3.x + k2.y*k3.y + k2.z*k3.z + k2.w*k3.w;

#pragma unroll
        for (int off = 16; off > 0; off >>= 1) {
            G01 += __shfl_xor_sync(0xffffffffu, G01, off);
            G02 += __shfl_xor_sync(0xffffffffu, G02, off);
            G03 += __shfl_xor_sync(0xffffffffu, G03, off);
            G12 += __shfl_xor_sync(0xffffffffu, G12, off);
            G13 += __shfl_xor_sync(0xffffffffu, G13, off);
            G23 += __shfl_xor_sync(0xffffffffu, G23, off);
        }
        if (lane == 0) {
            float* gp = gram + (size_t)cid * 8;
            *(float4*)(gp)     = make_float4(G01, G02, G03, G12);
            *(float4*)(gp + 4) = make_float4(G13, G23, 0.0f, 0.0f);
        }
        return;
    }

    // ---- transpose: 32x32 tiles, q then v ----
    __shared__ float ts[32][33];
    const int tt = blockIdx.x - 2048;              // 0 .. 16383
    const int tensor = tt >> 13;                   // 0 = q, 1 = v
    const int rem = tt & 8191;
    const int bb = rem >> 9;                       // batch
    const int tile = rem & 511;
    const int ct = tile >> 7;                      // col tile 0..3
    const int tk = tile & 127;                     // token tile 0..127

    const float* src = tensor ? v : q;
    float* dst = tensor ? vT : qT;
    const size_t sbase = (size_t)bb * T_ * C_;

    const int ty = tid >> 5, lane = tid & 31;
#pragma unroll
    for (int r = 0; r < 4; ++r) {
        const int row = tk*32 + ty + r*8;          // token
        ts[ty + r*8][lane] = src[sbase + (size_t)row * C_ + ct*32 + lane];
    }
    __syncthreads();
#pragma unroll
    for (int r = 0; r < 4; ++r) {
        const int c = ct*32 + ty + r*8;            // channel
        dst[sbase + (size_t)c * T_ + tk*32 + lane] = ts[lane][ty + r*8];
    }
}

// =============================================================================
// Chunked (L=4) gated delta-rule recurrence, GROUPS=16, one row per warp.
// qT/vT transposed loads; barrier + o-flush every 2 chunks (drift-tolerant).
// Dynamic smem: osh[2 bufs][8 steps][8 warps][128 cols] = 64 KB.
// =============================================================================
struct ChunkRegs {
    float k[LCH][4];
    float q[LCH], v[LCH], a[LCH], b[LCH];
    float G[6];
};

__device__ __forceinline__ float red32(float x) {
    x += __shfl_xor_sync(0xffffffffu, x, 1);
    x += __shfl_xor_sync(0xffffffffu, x, 2);
    x += __shfl_xor_sync(0xffffffffu, x, 4);
    x += __shfl_xor_sync(0xffffffffu, x, 8);
    x += __shfl_xor_sync(0xffffffffu, x, 16);
    return x;
}

__device__ __forceinline__ void load_chunk(int tcN,
                                           const float* __restrict__ kg,
                                           const float* __restrict__ qTg,
                                           const float* __restrict__ vTg,
                                           const float* __restrict__ ag,
                                           const float* __restrict__ bg,
                                           const float* __restrict__ gramb,
                                           int jb, ChunkRegs& R)
{
#pragma unroll
    for (int t4 = 0; t4 < LCH; ++t4) {
        const size_t off = ((size_t)tcN*LCH + t4) * C_;
        float4 kx = *(const float4*)(kg + off + jb);
        R.k[t4][0]=kx.x; R.k[t4][1]=kx.y; R.k[t4][2]=kx.z; R.k[t4][3]=kx.w;
    }
    // warp-uniform transposed loads: 4 steps contiguous
    float4 q4 = *(const float4*)(qTg + tcN*LCH);
    float4 v4 = *(const float4*)(vTg + tcN*LCH);
    R.q[0]=q4.x; R.q[1]=q4.y; R.q[2]=q4.z; R.q[3]=q4.w;
    R.v[0]=v4.x; R.v[1]=v4.y; R.v[2]=v4.z; R.v[3]=v4.w;
    float4 a4 = *(const float4*)(ag + tcN*LCH);
    float4 b4 = *(const float4*)(bg + tcN*LCH);
    R.a[0]=a4.x; R.a[1]=a4.y; R.a[2]=a4.z; R.a[3]=a4.w;
    R.b[0]=b4.x; R.b[1]=b4.y; R.b[2]=b4.z; R.b[3]=b4.w;
    float4 ga = *(const float4*)(gramb + (size_t)tcN * 8);
    float4 gb = *(const float4*)(gramb + (size_t)tcN * 8 + 4);
    R.G[0]=ga.x; R.G[1]=ga.y; R.G[2]=ga.z; R.G[3]=ga.w;
    R.G[4]=gb.x; R.G[5]=gb.y;
}

// osh layout: [buf(2)][step(8)][warp(8)][col(128)]
__device__ __forceinline__ void chunk_body(int tc, int buf, int cig, bool pf,
                                           float S[4], ChunkRegs& cur, ChunkRegs& nxt,
                                           const float* __restrict__ kg,
                                           const float* __restrict__ qTg,
                                           const float* __restrict__ vTg,
                                           const float* __restrict__ ag,
                                           const float* __restrict__ bg,
                                           const float* __restrict__ gramb,
                                           int jb, int warp, int lane,
                                           float* __restrict__ osh)
{
    // --- phase 1: m partials vs chunk-start S ---
    float m[LCH];
#pragma unroll
    for (int t4 = 0; t4 < LCH; ++t4) {
        float s = 0.0f;
#pragma unroll
        for (int jj = 0; jj < 4; ++jj) s += S[jj] * cur.k[t4][jj];
        m[t4] = s;
    }

    if (pf) load_chunk(tc + 1, kg, qTg, vTg, ag, bg, gramb, jb, nxt);

    m[0]=red32(m[0]); m[1]=red32(m[1]); m[2]=red32(m[2]); m[3]=red32(m[3]);

    // --- phase 2: exact scalar recursion for c_tau ---
    const float a0=cur.a[0], a1=cur.a[1], a2=cur.a[2], a3=cur.a[3];
    const float G01=cur.G[0], G02=cur.G[1], G03=cur.G[2];
    const float G12=cur.G[3], G13=cur.G[4], G23=cur.G[5];
    const float u0 = m[0];
    const float c0 = cur.b[0] * (cur.v[0] - a0*u0);
    const float u1 = a0*m[1] + c0*G01;
    const float c1 = cur.b[1] * (cur.v[1] - a1*u1);
    const float a01 = a0*a1;
    const float u2 = a01*m[2] + a1*c0*G02 + c1*G12;
    const float c2 = cur.b[2] * (cur.v[2] - a2*u2);
    const float u3 = a01*a2*m[3] + a1*a2*c0*G03 + a2*c1*G13 + c2*G23;
    const float c3 = cur.b[3] * (cur.v[3] - a3*u3);
    const float cc[LCH] = {c0, c1, c2, c3};

    // --- phase 3: per-step register updates + o partials ---
#pragma unroll
    for (int t4 = 0; t4 < LCH; ++t4) {
        float po[4];
#pragma unroll
        for (int jj = 0; jj < 4; ++jj) {
            S[jj] = cur.a[t4] * S[jj] + cc[t4] * cur.k[t4][jj];
            po[jj] = cur.q[t4] * S[jj];
        }
        const int step = cig * LCH + t4;
        *(float4*)&osh[(((size_t)buf*8 + step)*8 + warp)*C_ + lane*4]
            = make_float4(po[0], po[1], po[2], po[3]);
    }
    // no barrier here — flushed per 2-chunk group by caller
}

__global__ __launch_bounds__(256, 2) void recurrence4(const float* __restrict__ qT,
                                                      const float* __restrict__ k,
                                                      const float* __restrict__ vT,
                                                      const float* __restrict__ al,
                                                      const float* __restrict__ be,
                                                      const float* __restrict__ gram,
                                                      float* __restrict__ opart)
{
    extern __shared__ float osh[];   // [2][8][8][128] = 64 KB

    const int g   = blockIdx.x;
    const int bb  = blockIdx.y;
    const int tid = threadIdx.x;
    const int warp = tid >> 5, lane = tid & 31;
    const int i  = g * 8 + warp;
    const int jb = lane * 4;

    const size_t bbase = (size_t)bb * T_ * C_;
    const size_t sbase = (size_t)bb * T_;
    const float* kg  = k + bbase;
    const float* qTg = qT + bbase + (size_t)i * T_;
    const float* vTg = vT + bbase + (size_t)i * T_;
    const float* ag = al + sbase;
    const float* bg = be + sbase;
    const float* gramb = gram + (size_t)bb * NCH * 8;
    float* op = opart + (size_t)g * M_ * C_ + bbase;

    float S[4];
#pragma unroll
    for (int jj = 0; jj < 4; ++jj) S[jj] = 0.0f;

    ChunkRegs RA, RB;
    load_chunk(0, kg, qTg, vTg, ag, bg, gramb, jb, RA);

    const int fst = tid >> 5;            // flush step 0..7
    const int fc4 = (tid & 31) * 4;      // flush col group

#pragma unroll 1
    for (int tc = 0; tc < NCH; tc += 2) {
        const int buf = (tc >> 1) & 1;
        chunk_body(tc,   buf, 0, true,          S, RA, RB, kg, qTg, vTg, ag, bg, gramb, jb, warp, lane, osh);
        chunk_body(tc+1, buf, 1, (tc+2) < NCH,  S, RB, RA, kg, qTg, vTg, ag, bg, gramb, jb, warp, lane, osh);
        __syncthreads();   // one barrier per 2 chunks

        // flush: 8 steps x 128 cols, 256 threads -> 1 float4 slot each
        const float* base = &osh[((size_t)buf*8 + fst)*8*C_];
        float4 acc = *(const float4*)(base + fc4);
#pragma unroll
        for (int w = 1; w < 8; ++w) {
            const float4 p = *(const float4*)(base + w*C_ + fc4);
            acc.x += p.x; acc.y += p.y; acc.z += p.z; acc.w += p.w;
        }
        *(float4*)(op + ((size_t)tc*LCH + fst) * C_ + fc4) = acc;
    }
}

// =============================================================================
// combine: o = (sum over groups of opart) * gate -> bf16 hi/lo split
// =============================================================================
__global__ __launch_bounds__(256) void combine_split(const float* __restrict__ opart,
                                                     const float* __restrict__ gate,
                                                     bf16* __restrict__ oh,
                                                     bf16* __restrict__ ol)
{
    const size_t idx = ((size_t)blockIdx.x * 256 + threadIdx.x) * 4;
    float4 s = make_float4(0.f, 0.f, 0.f, 0.f);
#pragma unroll
    for (int g = 0; g < GROUPS; ++g) {
        float4 p = *(const float4*)(opart + (size_t)g * M_ * C_ + idx);
        s.x += p.x; s.y += p.y; s.z += p.z; s.w += p.w;
    }
    float4 gt = *(const float4*)(gate + idx);
    s.x *= gt.x; s.y *= gt.y; s.z *= gt.z; s.w *= gt.w;

    bf16 h0 = __float2bfloat16_rn(s.x);
    bf16 h1 = __float2bfloat16_rn(s.y);
    bf16 h2 = __float2bfloat16_rn(s.z);
    bf16 h3 = __float2bfloat16_rn(s.w);
    bf16 l0 = __float2bfloat16_rn(s.x - __bfloat162float(h0));
    bf16 l1 = __float2bfloat16_rn(s.y - __bfloat162float(h1));
    bf16 l2 = __float2bfloat16_rn(s.z - __bfloat162float(h2));
    bf16 l3 = __float2bfloat16_rn(s.w - __bfloat162float(h3));
    __nv_bfloat162* H = (__nv_bfloat162*)(oh + idx);
    __nv_bfloat162* L = (__nv_bfloat162*)(ol + idx);
    H[0] = __nv_bfloat162(h0, h1); H[1] = __nv_bfloat162(h2, h3);
    L[0] = __nv_bfloat162(l0, l1); L[1] = __nv_bfloat162(l2, l3);
}

// =============================================================================
extern "C" void kernel_launch(void* const* d_in, const int* in_sizes, int n_in,
                              void* d_out, int out_size)
{
    const float* x  = (const float*)d_in[0];
    const float* Wq = (const float*)d_in[1];
    const float* bq = (const float*)d_in[2];
    const float* Wk = (const float*)d_in[3];
    const float* bk = (const float*)d_in[4];
    const float* Wv = (const float*)d_in[5];
    const float* bv = (const float*)d_in[6];
    const float* Wa = (const float*)d_in[7];
    const float* ba = (const float*)d_in[8];
    const float* Wb = (const float*)d_in[9];
    const float* bb = (const float*)d_in[10];
    const float* Wg = (const float*)d_in[11];
    const float* bg = (const float*)d_in[12];
    const float* Wo = (const float*)d_in[13];
    const float* bo = (const float*)d_in[14];
    float* out = (float*)d_out;

    float *q, *k, *v, *g, *qT, *vT, *a, *b, *op, *gram;
    bf16 *xh, *xl, *oh, *ol;
    bf16 *wqh, *wql, *wkh, *wkl, *wvh, *wvl, *wgh, *wgl, *woh, *wol;
    cudaGetSymbolAddress((void**)&q,  g_q);
    cudaGetSymbolAddress((void**)&k,  g_k);
    cudaGetSymbolAddress((void**)&v,  g_v);
    cudaGetSymbolAddress((void**)&g,  g_g);
    cudaGetSymbolAddress((void**)&qT, g_qT);
    cudaGetSymbolAddress((void**)&vT, g_vT);
    cudaGetSymbolAddress((void**)&a,  g_a);
    cudaGetSymbolAddress((void**)&b,  g_b);
    cudaGetSymbolAddress((void**)&op, g_opart);
    cudaGetSymbolAddress((void**)&gram, g_gram);
    cudaGetSymbolAddress((void**)&xh, g_xh);
    cudaGetSymbolAddress((void**)&xl, g_xl);
    cudaGetSymbolAddress((void**)&oh, g_oh);
    cudaGetSymbolAddress((void**)&ol, g_ol);
    cudaGetSymbolAddress((void**)&wqh, g_wqh); cudaGetSymbolAddress((void**)&wql, g_wql);
    cudaGetSymbolAddress((void**)&wkh, g_wkh); cudaGetSymbolAddress((void**)&wkl, g_wkl);
    cudaGetSymbolAddress((void**)&wvh, g_wvh); cudaGetSymbolAddress((void**)&wvl, g_wvl);
    cudaGetSymbolAddress((void**)&wgh, g_wgh); cudaGetSymbolAddress((void**)&wgl, g_wgl);
    cudaGetSymbolAddress((void**)&woh, g_woh); cudaGetSymbolAddress((void**)&wol, g_wol);

    const dim3 blk(256);
    const int OSH = 2*8*8*C_*4;   // 64 KB dynamic smem for recurrence

    cudaFuncSetAttribute(recurrence4, cudaFuncAttributeMaxDynamicSharedMemorySize, OSH);

    // (0) fused prep: alpha/beta + x split + 5 weight splits
    fused_prep<<<M_/8 + 5*128, blk>>>(x, Wa, ba, Wb, bb, a, b, xh, xl,
                                      Wq, Wk, Wv, Wg, Wo,
                                      wqh, wql, wkh, wkl, wvh, wvl,
                                      wgh, wgl, woh, wol);

    // (1) fused 4-projection HMMA GEMM (k-norm + gate-sigmoid in epilogue)
    proj_gemm<<<dim3(4, M_/128), blk>>>(xh, xl,
                                        wqh, wql, wkh, wkl, wvh, wvl, wgh, wgl,
                                        bq, bk, bv, bg, q, k, v, g);

    // (2) gram + q/v transpose
    prep2<<<2048 + 16384, blk>>>(k, q, v, gram, qT, vT);

    // (3) chunked sequential recurrence (256 CTAs)  <- profiled launch
    recurrence4<<<dim3(GROUPS, B_), blk, OSH>>>(qT, k, vT, a, b, gram, op);

    // (4) group-sum + gate -> bf16 split
    combine_split<<<(M_*C_/4)/256, blk>>>(op, g, oh, ol);

    // (5) output projection (HMMA)
    out_gemm<<<dim3(D_/128, M_/128), blk>>>(oh, ol, woh, wol, bo, out);
}

// round 12
// speedup vs baseline: 1.0701x; 1.0701x over previous
#include <cuda_runtime.h>
#include <cuda_bf16.h>
#include <cstdint>

#define B_ 16
#define T_ 4096
#define D_ 1024
#define C_ 128
#define M_ (B_*T_)        // 65536 tokens
#define GROUPS 8          // row-groups (16 rows each; 2 rows per warp)
#define LCH 4             // chunk length inside recurrence
#define NCH (T_/LCH)      // 1024 chunks per sequence

typedef __nv_bfloat16 bf16;

// ---------------- scratch (static device globals; no allocation) -------------
__device__ float g_q[(size_t)M_*C_];
__device__ float g_k[(size_t)M_*C_];
__device__ float g_v[(size_t)M_*C_];
__device__ float g_g[(size_t)M_*C_];
__device__ float g_qT[(size_t)M_*C_];   // [B][C][T]
__device__ float g_vT[(size_t)M_*C_];   // [B][C][T]
__device__ float g_a[M_];
__device__ float g_b[M_];
__device__ float g_opart[(size_t)GROUPS*M_*C_];
__device__ float g_gram[(size_t)B_*NCH*8];

__device__ bf16 g_xh[(size_t)M_*D_];
__device__ bf16 g_xl[(size_t)M_*D_];
__device__ bf16 g_oh[(size_t)M_*C_];
__device__ bf16 g_ol[(size_t)M_*C_];
__device__ bf16 g_wqh[C_*D_], g_wql[C_*D_];
__device__ bf16 g_wkh[C_*D_], g_wkl[C_*D_];
__device__ bf16 g_wvh[C_*D_], g_wvl[C_*D_];
__device__ bf16 g_wgh[C_*D_], g_wgl[C_*D_];
__device__ bf16 g_woh[D_*C_], g_wol[D_*C_];

__device__ __forceinline__ float sigmoidf_(float x) { return 1.0f / (1.0f + expf(-x)); }

// =============================================================================
// fused_prep: blocks [0, M_/8)            -> alpha/beta + x hi/lo split
//             blocks [M_/8, M_/8 + 640)   -> weight hi/lo splits (5 matrices)
// =============================================================================
__global__ __launch_bounds__(256) void fused_prep(
    const float* __restrict__ x,
    const float* __restrict__ Wa, const float* __restrict__ ba,
    const float* __restrict__ Wb, const float* __restrict__ bb,
    float* __restrict__ a_out, float* __restrict__ b_out,
    bf16* __restrict__ xh, bf16* __restrict__ xl,
    const float* Wq, const float* Wk, const float* Wv, const float* Wg, const float* Wo,
    bf16* wqh, bf16* wql, bf16* wkh, bf16* wkl, bf16* wvh, bf16* wvl,
    bf16* wgh, bf16* wgl, bf16* woh, bf16* wol)
{
    const int tid = threadIdx.x;
    constexpr int NAB = M_/8;

    if (blockIdx.x >= NAB) {
        const int widx = blockIdx.x - NAB;
        const int mat  = widx >> 7;
        const float* in; bf16 *hi, *lo;
        if      (mat == 0) { in = Wq; hi = wqh; lo = wql; }
        else if (mat == 1) { in = Wk; hi = wkh; lo = wkl; }
        else if (mat == 2) { in = Wv; hi = wvh; lo = wvl; }
        else if (mat == 3) { in = Wg; hi = wgh; lo = wgl; }
        else               { in = Wo; hi = woh; lo = wol; }
        const int i = (widx & 127) * 256 + tid;
        float4 xv = *(const float4*)(in + (size_t)i * 4);
        bf16 h0 = __float2bfloat16_rn(xv.x);
        bf16 h1 = __float2bfloat16_rn(xv.y);
        bf16 h2 = __float2bfloat16_rn(xv.z);
        bf16 h3 = __float2bfloat16_rn(xv.w);
        bf16 l0 = __float2bfloat16_rn(xv.x - __bfloat162float(h0));
        bf16 l1 = __float2bfloat16_rn(xv.y - __bfloat162float(h1));
        bf16 l2 = __float2bfloat16_rn(xv.z - __bfloat162float(h2));
        bf16 l3 = __float2bfloat16_rn(xv.w - __bfloat162float(h3));
        __nv_bfloat162* H = (__nv_bfloat162*)(hi + (size_t)i * 4);
        __nv_bfloat162* L = (__nv_bfloat162*)(lo + (size_t)i * 4);
        H[0] = __nv_bfloat162(h0, h1); H[1] = __nv_bfloat162(h2, h3);
        L[0] = __nv_bfloat162(l0, l1); L[1] = __nv_bfloat162(l2, l3);
        return;
    }

    __shared__ __align__(16) float sWa[D_];
    __shared__ __align__(16) float sWb[D_];
    for (int i = tid; i < D_; i += 256) { sWa[i] = Wa[i]; sWb[i] = Wb[i]; }
    __syncthreads();

    const int warp = tid >> 5, lane = tid & 31;
    const int tok  = blockIdx.x * 8 + warp;
    const size_t base = (size_t)tok * D_;
    const float* xr = x + base;

    float da = 0.0f, db = 0.0f;
#pragma unroll
    for (int j = 0; j < 8; ++j) {
        const int off = j*128 + lane*4;
        float4 xv = *(const float4*)(xr  + off);
        float4 wa = *(const float4*)(sWa + off);
        float4 wb = *(const float4*)(sWb + off);
        da += xv.x*wa.x + xv.y*wa.y + xv.z*wa.z + xv.w*wa.w;
        db += xv.x*wb.x + xv.y*wb.y + xv.z*wb.z + xv.w*wb.w;

        bf16 h0 = __float2bfloat16_rn(xv.x);
        bf16 h1 = __float2bfloat16_rn(xv.y);
        bf16 h2 = __float2bfloat16_rn(xv.z);
        bf16 h3 = __float2bfloat16_rn(xv.w);
        bf16 l0 = __float2bfloat16_rn(xv.x - __bfloat162float(h0));
        bf16 l1 = __float2bfloat16_rn(xv.y - __bfloat162float(h1));
        bf16 l2 = __float2bfloat16_rn(xv.z - __bfloat162float(h2));
        bf16 l3 = __float2bfloat16_rn(xv.w - __bfloat162float(h3));
        __nv_bfloat162* H = (__nv_bfloat162*)(xh + base + off);
        __nv_bfloat162* L = (__nv_bfloat162*)(xl + base + off);
        H[0] = __nv_bfloat162(h0, h1); H[1] = __nv_bfloat162(h2, h3);
        L[0] = __nv_bfloat162(l0, l1); L[1] = __nv_bfloat162(l2, l3);
    }
#pragma unroll
    for (int off = 16; off > 0; off >>= 1) {
        da += __shfl_xor_sync(0xffffffffu, da, off);
        db += __shfl_xor_sync(0xffffffffu, db, off);
    }
    if (lane == 0) {
        a_out[tok] = sigmoidf_(da + ba[0]);
        b_out[tok] = sigmoidf_(db + bb[0]);
    }
}

// =============================================================================
// Tensor-core NT GEMM core (HMMA mma.sync).
// =============================================================================
__device__ __forceinline__ void ldsm4(uint32_t& r0, uint32_t& r1,
                                      uint32_t& r2, uint32_t& r3, uint32_t a)
{
    asm volatile("ldmatrix.sync.aligned.m8n8.x4.shared.b16 {%0,%1,%2,%3}, [%4];"
                 : "=r"(r0), "=r"(r1), "=r"(r2), "=r"(r3) : "r"(a));
}

__device__ __forceinline__ void mma16816(float c[4], const uint32_t a[4], const uint32_t b[2])
{
    asm volatile("mma.sync.aligned.m16n8k16.row.col.f32.bf16.bf16.f32 "
                 "{%0,%1,%2,%3}, {%4,%5,%6,%7}, {%8,%9}, {%0,%1,%2,%3};"
                 : "+f"(c[0]), "+f"(c[1]), "+f"(c[2]), "+f"(c[3])
                 : "r"(a[0]), "r"(a[1]), "r"(a[2]), "r"(a[3]), "r"(b[0]), "r"(b[1]));
}

template<int KDIM>
__device__ __forceinline__ void mma_loop(const bf16* __restrict__ A0,
                                         const bf16* __restrict__ A1,
                                         const bf16* __restrict__ A2,
                                         const bf16* __restrict__ B0,
                                         const bf16* __restrict__ B1,
                                         const bf16* __restrict__ B2,
                                         int m0, uint4* sA, uint4* sB,
                                         float acc[4][4][4])
{
    constexpr int KIT = KDIM / 32;
    constexpr int TOT = 3 * KIT;
    const int tid  = threadIdx.x;
    const int lane = tid & 31, warp = tid >> 5;
    const int wm = warp & 1, wn = warp >> 1;

    const int r0_ = tid >> 2,        u_ = tid & 3;
    const int r1_ = 64 + (tid >> 2);
    const int st0 = r0_ * 4 + (u_ ^ ((r0_ >> 1) & 3));
    const int st1 = r1_ * 4 + (u_ ^ ((r1_ >> 1) & 3));

    const uint32_t saB = (uint32_t)__cvta_generic_to_shared(sA);
    const uint32_t sbB = (uint32_t)__cvta_generic_to_shared(sB);

    uint4 ra0, ra1, rb0, rb1;
    {
        ra0 = *(const uint4*)(A0 + (size_t)(m0 + r0_) * KDIM + u_ * 8);
        ra1 = *(const uint4*)(A0 + (size_t)(m0 + r1_) * KDIM + u_ * 8);
        rb0 = *(const uint4*)(B0 + (size_t)r0_ * KDIM + u_ * 8);
        rb1 = *(const uint4*)(B0 + (size_t)r1_ * KDIM + u_ * 8);
    }

#pragma unroll 1
    for (int it = 0; it < TOT; ++it) {
        const int buf = it & 1;
        sA[buf * 512 + st0] = ra0; sA[buf * 512 + st1] = ra1;
        sB[buf * 512 + st0] = rb0; sB[buf * 512 + st1] = rb1;
        __syncthreads();

        if (it + 1 < TOT) {
            const int nit = it + 1;
            const int p = nit / KIT;
            const int kk = (nit - p * KIT) * 32;
            const bf16* Ap = (p == 0) ? A0 : (p == 1) ? A1 : A2;
            const bf16* Bp = (p == 0) ? B0 : (p == 1) ? B1 : B2;
            ra0 = *(const uint4*)(Ap + (size_t)(m0 + r0_) * KDIM + kk + u_ * 8);
            ra1 = *(const uint4*)(Ap + (size_t)(m0 + r1_) * KDIM + kk + u_ * 8);
            rb0 = *(const uint4*)(Bp + (size_t)r0_ * KDIM + kk + u_ * 8);
            rb1 = *(const uint4*)(Bp + (size_t)r1_ * KDIM + kk + u_ * 8);
        }

        const uint32_t aBase = saB + buf * 8192;
        const uint32_t bBase = sbB + buf * 8192;
#pragma unroll
        for (int ks = 0; ks < 2; ++ks) {
            uint32_t af[4][4], bfr[4][2];
#pragma unroll
            for (int mt = 0; mt < 4; ++mt) {
                const int row = wm * 64 + mt * 16 + (lane & 15);
                const int u = ks * 2 + (lane >> 4);
                ldsm4(af[mt][0], af[mt][1], af[mt][2], af[mt][3],
                      aBase + (uint32_t)((row * 4 + (u ^ ((row >> 1) & 3))) * 16));
            }
#pragma unroll
            for (int j = 0; j < 2; ++j) {
                const int gq = lane >> 3;
                const int n = wn * 32 + j * 16 + ((gq >> 1) << 3) + (lane & 7);
                const int u = ks * 2 + (gq & 1);
                uint32_t t0, t1, t2, t3;
                ldsm4(t0, t1, t2, t3,
                      bBase + (uint32_t)((n * 4 + (u ^ ((n >> 1) & 3))) * 16));
                bfr[j*2][0] = t0; bfr[j*2][1] = t1;
                bfr[j*2+1][0] = t2; bfr[j*2+1][1] = t3;
            }
#pragma unroll
            for (int mt = 0; mt < 4; ++mt)
#pragma unroll
                for (int nt = 0; nt < 4; ++nt)
                    mma16816(acc[mt][nt], af[mt], bfr[nt]);
        }
    }
}

// =============================================================================
// Fused 4-projection GEMM (HMMA).
// =============================================================================
__global__ __launch_bounds__(256, 2) void proj_gemm(
    const bf16* __restrict__ xh, const bf16* __restrict__ xl,
    const bf16* wqh, const bf16* wql, const bf16* wkh, const bf16* wkl,
    const bf16* wvh, const bf16* wvl, const bf16* wgh, const bf16* wgl,
    const float* bq, const float* bk, const float* bv, const float* bg,
    float* outq, float* outk, float* outv, float* outg)
{
    __shared__ uint4 sA[1024];
    __shared__ uint4 sB[1024];
    __shared__ float snorm[4][128];

    const int proj = blockIdx.x;
    const int m0 = blockIdx.y * 128;
    const bf16 *Bh, *Bl; const float* bias; float* C;
    if      (proj == 0) { Bh = wqh; Bl = wql; bias = bq; C = outq; }
    else if (proj == 1) { Bh = wkh; Bl = wkl; bias = bk; C = outk; }
    else if (proj == 2) { Bh = wvh; Bl = wvl; bias = bv; C = outv; }
    else                { Bh = wgh; Bl = wgl; bias = bg; C = outg; }

    float acc[4][4][4];
#pragma unroll
    for (int mt = 0; mt < 4; ++mt)
#pragma unroll
        for (int nt = 0; nt < 4; ++nt)
#pragma unroll
            for (int c = 0; c < 4; ++c) acc[mt][nt][c] = 0.0f;

    mma_loop<D_>(xh, xh, xl, Bh, Bl, Bh, m0, sA, sB, acc);

    const int lane = threadIdx.x & 31, warp = threadIdx.x >> 5;
    const int wm = warp & 1, wn = warp >> 1;

#pragma unroll
    for (int nt = 0; nt < 4; ++nt) {
        const int col = wn * 32 + nt * 8 + (lane & 3) * 2;
        const float b0 = bias[col], b1 = bias[col + 1];
#pragma unroll
        for (int mt = 0; mt < 4; ++mt) {
            acc[mt][nt][0] += b0; acc[mt][nt][1] += b1;
            acc[mt][nt][2] += b0; acc[mt][nt][3] += b1;
        }
    }

    if (proj == 3) {
#pragma unroll
        for (int mt = 0; mt < 4; ++mt)
#pragma unroll
            for (int nt = 0; nt < 4; ++nt)
#pragma unroll
                for (int c = 0; c < 4; ++c)
                    acc[mt][nt][c] = sigmoidf_(acc[mt][nt][c]);
    }

    if (proj == 1) {
#pragma unroll
        for (int mt = 0; mt < 4; ++mt)
#pragma unroll
            for (int h = 0; h < 2; ++h) {
                float ss = 0.0f;
#pragma unroll
                for (int nt = 0; nt < 4; ++nt) {
                    ss += acc[mt][nt][2*h] * acc[mt][nt][2*h];
                    ss += acc[mt][nt][2*h+1] * acc[mt][nt][2*h+1];
                }
                ss += __shfl_xor_sync(0xffffffffu, ss, 1);
                ss += __shfl_xor_sync(0xffffffffu, ss, 2);
                if ((lane & 3) == 0)
                    snorm[wn][wm*64 + mt*16 + h*8 + (lane >> 2)] = ss;
            }
        __syncthreads();
#pragma unroll
        for (int mt = 0; mt < 4; ++mt)
#pragma unroll
            for (int h = 0; h < 2; ++h) {
                const int row = wm*64 + mt*16 + h*8 + (lane >> 2);
                const float s = snorm[0][row] + snorm[1][row] + snorm[2][row] + snorm[3][row];
                const float inv = 1.0f / fmaxf(sqrtf(s), 1e-12f);
#pragma unroll
                for (int nt = 0; nt < 4; ++nt) {
                    acc[mt][nt][2*h]   *= inv;
                    acc[mt][nt][2*h+1] *= inv;
                }
            }
    }

#pragma unroll
    for (int mt = 0; mt < 4; ++mt) {
        const int r = m0 + wm*64 + mt*16 + (lane >> 2);
#pragma unroll
        for (int nt = 0; nt < 4; ++nt) {
            const int col = wn*32 + nt*8 + (lane & 3)*2;
            *(float2*)(C + (size_t)r * C_ + col)       = make_float2(acc[mt][nt][0], acc[mt][nt][1]);
            *(float2*)(C + (size_t)(r+8) * C_ + col)   = make_float2(acc[mt][nt][2], acc[mt][nt][3]);
        }
    }
}

// =============================================================================
// Output GEMM (HMMA).
// =============================================================================
__global__ __launch_bounds__(256, 2) void out_gemm(
    const bf16* __restrict__ oh, const bf16* __restrict__ ol,
    const bf16* __restrict__ woh, const bf16* __restrict__ wol,
    const float* __restrict__ bo, float* __restrict__ out)
{
    __shared__ uint4 sA[1024];
    __shared__ uint4 sB[1024];

    const int n0 = blockIdx.x * 128;
    const int m0 = blockIdx.y * 128;
    const bf16* Bh = woh + (size_t)n0 * C_;
    const bf16* Bl = wol + (size_t)n0 * C_;

    float acc[4][4][4];
#pragma unroll
    for (int mt = 0; mt < 4; ++mt)
#pragma unroll
        for (int nt = 0; nt < 4; ++nt)
#pragma unroll
            for (int c = 0; c < 4; ++c) acc[mt][nt][c] = 0.0f;

    mma_loop<C_>(oh, oh, ol, Bh, Bl, Bh, m0, sA, sB, acc);

    const int lane = threadIdx.x & 31, warp = threadIdx.x >> 5;
    const int wm = warp & 1, wn = warp >> 1;

#pragma unroll
    for (int mt = 0; mt < 4; ++mt) {
        const int r = m0 + wm*64 + mt*16 + (lane >> 2);
#pragma unroll
        for (int nt = 0; nt < 4; ++nt) {
            const int col = n0 + wn*32 + nt*8 + (lane & 3)*2;
            const float b0 = bo[col], b1 = bo[col + 1];
            *(float2*)(out + (size_t)r * D_ + col)
                = make_float2(acc[mt][nt][0] + b0, acc[mt][nt][1] + b1);
            *(float2*)(out + (size_t)(r+8) * D_ + col)
                = make_float2(acc[mt][nt][2] + b0, acc[mt][nt][3] + b1);
        }
    }
}

// =============================================================================
// prep2: blocks [0, 2048)          -> chunk Gram precompute (1 warp per chunk)
//        blocks [2048, 2048+16384) -> q/v transpose to [B][C][T]
// =============================================================================
__global__ __launch_bounds__(256) void prep2(const float* __restrict__ k,
                                             const float* __restrict__ q,
                                             const float* __restrict__ v,
                                             float* __restrict__ gram,
                                             float* __restrict__ qT,
                                             float* __restrict__ vT)
{
    const int tid = threadIdx.x;

    if (blockIdx.x < 2048) {
        const int warp = tid >> 5, lane = tid & 31;
        const int cid = blockIdx.x * 8 + warp;
        const int bb = cid >> 10, tc = cid & 1023;
        const float* kg = k + ((size_t)bb * T_ + (size_t)tc * LCH) * C_ + lane * 4;

        float4 k0 = *(const float4*)(kg + 0*C_);
        float4 k1 = *(const float4*)(kg + 1*C_);
        float4 k2 = *(const float4*)(kg + 2*C_);
        float4 k3 = *(const float4*)(kg + 3*C_);

        float G01 = k0.x*k1.x + k0.y*k1.y + k0.z*k1.z + k0.w*k1.w;
        float G02 = k0.x*k2.x + k0.y*k2.y + k0.z*k2.z + k0.w*k2.w;
        float G03 = k0.x*k3.x + k0.y*k3.y + k0.z*k3.z + k0.w*k3.w;
        float G12 = k1.x*k2.x + k1.y*k2.y + k1.z*k2.z + k1.w*k2.w;
        float G13 = k1.x*k3.x + k1.y*k3.y + k1.z*k3.z + k1.w*k3.w;
        float G23 = k2.x*k3.x + k2.y*k3.y + k2.z*k3.z + k2.w*k3.w;

#pragma unroll
        for (int off = 16; off > 0; off >>= 1) {
            G01 += __shfl_xor_sync(0xffffffffu, G01, off);
            G02 += __shfl_xor_sync(0xffffffffu, G02, off);
            G03 += __shfl_xor_sync(0xffffffffu, G03, off);
            G12 += __shfl_xor_sync(0xffffffffu, G12, off);
            G13 += __shfl_xor_sync(0xffffffffu, G13, off);
            G23 += __shfl_xor_sync(0xffffffffu, G23, off);
        }
        if (lane == 0) {
            float* gp = gram + (size_t)cid * 8;
            *(float4*)(gp)     = make_float4(G01, G02, G03, G12);
            *(float4*)(gp + 4) = make_float4(G13, G23, 0.0f, 0.0f);
        }
        return;
    }

    __shared__ float ts[32][33];
    const int tt = blockIdx.x - 2048;
    const int tensor = tt >> 13;
    const int rem = tt & 8191;
    const int bb = rem >> 9;
    const int tile = rem & 511;
    const int ct = tile >> 7;
    const int tk = tile & 127;

    const float* src = tensor ? v : q;
    float* dst = tensor ? vT : qT;
    const size_t sbase = (size_t)bb * T_ * C_;

    const int ty = tid >> 5, lane = tid & 31;
#pragma unroll
    for (int r = 0; r < 4; ++r) {
        const int row = tk*32 + ty + r*8;
        ts[ty + r*8][lane] = src[sbase + (size_t)row * C_ + ct*32 + lane];
    }
    __syncthreads();
#pragma unroll
    for (int r = 0; r < 4; ++r) {
        const int c = ct*32 + ty + r*8;
        dst[sbase + (size_t)c * T_ + tk*32 + lane] = ts[lane][ty + r*8];
    }
}

// =============================================================================
// Chunked (L=4) gated delta-rule recurrence, GROUPS=8, TWO ROWS PER WARP.
// Grid (8, 16) = 128 CTAs, 1/SM. Warp w owns rows i0 = g*16+2w, i1 = i0+1;
// lane owns 4 cols of each row. po = q0*S0 + q1*S1 summed in registers ->
// per-warp k/STS/LDS traffic amortized over 2 rows (total L1 traffic halved).
// =============================================================================
struct ChunkRegs {
    float k[LCH][4];
    float q0[LCH], q1[LCH], v0[LCH], v1[LCH], a[LCH], b[LCH];
    float G[6];
};

__device__ __forceinline__ float red32(float x) {
    x += __shfl_xor_sync(0xffffffffu, x, 1);
    x += __shfl_xor_sync(0xffffffffu, x, 2);
    x += __shfl_xor_sync(0xffffffffu, x, 4);
    x += __shfl_xor_sync(0xffffffffu, x, 8);
    x += __shfl_xor_sync(0xffffffffu, x, 16);
    return x;
}

__device__ __forceinline__ void load_chunk(int tcN,
                                           const float* __restrict__ kg,
                                           const float* __restrict__ qT0,
                                           const float* __restrict__ qT1,
                                           const float* __restrict__ vT0,
                                           const float* __restrict__ vT1,
                                           const float* __restrict__ ag,
                                           const float* __restrict__ bg,
                                           const float* __restrict__ gramb,
                                           int jb, ChunkRegs& R)
{
#pragma unroll
    for (int t4 = 0; t4 < LCH; ++t4) {
        const size_t off = ((size_t)tcN*LCH + t4) * C_;
        float4 kx = *(const float4*)(kg + off + jb);
        R.k[t4][0]=kx.x; R.k[t4][1]=kx.y; R.k[t4][2]=kx.z; R.k[t4][3]=kx.w;
    }
    float4 q4 = *(const float4*)(qT0 + tcN*LCH);
    R.q0[0]=q4.x; R.q0[1]=q4.y; R.q0[2]=q4.z; R.q0[3]=q4.w;
    q4 = *(const float4*)(qT1 + tcN*LCH);
    R.q1[0]=q4.x; R.q1[1]=q4.y; R.q1[2]=q4.z; R.q1[3]=q4.w;
    float4 v4 = *(const float4*)(vT0 + tcN*LCH);
    R.v0[0]=v4.x; R.v0[1]=v4.y; R.v0[2]=v4.z; R.v0[3]=v4.w;
    v4 = *(const float4*)(vT1 + tcN*LCH);
    R.v1[0]=v4.x; R.v1[1]=v4.y; R.v1[2]=v4.z; R.v1[3]=v4.w;
    float4 a4 = *(const float4*)(ag + tcN*LCH);
    float4 b4 = *(const float4*)(bg + tcN*LCH);
    R.a[0]=a4.x; R.a[1]=a4.y; R.a[2]=a4.z; R.a[3]=a4.w;
    R.b[0]=b4.x; R.b[1]=b4.y; R.b[2]=b4.z; R.b[3]=b4.w;
    float4 ga = *(const float4*)(gramb + (size_t)tcN * 8);
    float4 gb = *(const float4*)(gramb + (size_t)tcN * 8 + 4);
    R.G[0]=ga.x; R.G[1]=ga.y; R.G[2]=ga.z; R.G[3]=ga.w;
    R.G[4]=gb.x; R.G[5]=gb.y;
}

// exact per-row scalar recursion (shared a,b,G; row-specific m,v)
__device__ __forceinline__ void row_recursion(const ChunkRegs& cur,
                                              const float m[LCH], const float* vv,
                                              float cc[LCH])
{
    const float a0=cur.a[0], a1=cur.a[1], a2=cur.a[2], a3=cur.a[3];
    const float G01=cur.G[0], G02=cur.G[1], G03=cur.G[2];
    const float G12=cur.G[3], G13=cur.G[4], G23=cur.G[5];
    const float u0 = m[0];
    cc[0] = cur.b[0] * (vv[0] - a0*u0);
    const float u1 = a0*m[1] + cc[0]*G01;
    cc[1] = cur.b[1] * (vv[1] - a1*u1);
    const float a01 = a0*a1;
    const float u2 = a01*m[2] + a1*cc[0]*G02 + cc[1]*G12;
    cc[2] = cur.b[2] * (vv[2] - a2*u2);
    const float u3 = a01*a2*m[3] + a1*a2*cc[0]*G03 + a2*cc[1]*G13 + cc[2]*G23;
    cc[3] = cur.b[3] * (vv[3] - a3*u3);
}

// osh layout: [buf(2)][step(8)][warp(8)][col(128)]
__device__ __forceinline__ void chunk_body(int tc, int buf, int cig, bool pf,
                                           float S0[4], float S1[4],
                                           ChunkRegs& cur, ChunkRegs& nxt,
                                           const float* __restrict__ kg,
                                           const float* __restrict__ qT0,
                                           const float* __restrict__ qT1,
                                           const float* __restrict__ vT0,
                                           const float* __restrict__ vT1,
                                           const float* __restrict__ ag,
                                           const float* __restrict__ bg,
                                           const float* __restrict__ gramb,
                                           int jb, int warp, int lane,
                                           float* __restrict__ osh)
{
    // --- phase 1: m partials vs chunk-start S for both rows ---
    float m0[LCH], m1[LCH];
#pragma unroll
    for (int t4 = 0; t4 < LCH; ++t4) {
        float s0 = 0.0f, s1 = 0.0f;
#pragma unroll
        for (int jj = 0; jj < 4; ++jj) {
            s0 += S0[jj] * cur.k[t4][jj];
            s1 += S1[jj] * cur.k[t4][jj];
        }
        m0[t4] = s0; m1[t4] = s1;
    }

    if (pf) load_chunk(tc + 1, kg, qT0, qT1, vT0, vT1, ag, bg, gramb, jb, nxt);

    // --- 8 independent full-warp reductions ---
    m0[0]=red32(m0[0]); m0[1]=red32(m0[1]); m0[2]=red32(m0[2]); m0[3]=red32(m0[3]);
    m1[0]=red32(m1[0]); m1[1]=red32(m1[1]); m1[2]=red32(m1[2]); m1[3]=red32(m1[3]);

    // --- phase 2: exact scalar recursion per row ---
    float cc0[LCH], cc1[LCH];
    row_recursion(cur, m0, cur.v0, cc0);
    row_recursion(cur, m1, cur.v1, cc1);

    // --- phase 3: per-step register updates + register-summed o partials ---
#pragma unroll
    for (int t4 = 0; t4 < LCH; ++t4) {
        float po[4];
#pragma unroll
        for (int jj = 0; jj < 4; ++jj) {
            S0[jj] = cur.a[t4] * S0[jj] + cc0[t4] * cur.k[t4][jj];
            S1[jj] = cur.a[t4] * S1[jj] + cc1[t4] * cur.k[t4][jj];
            po[jj] = cur.q0[t4] * S0[jj] + cur.q1[t4] * S1[jj];
        }
        const int step = cig * LCH + t4;
        *(float4*)&osh[(((size_t)buf*8 + step)*8 + warp)*C_ + lane*4]
            = make_float4(po[0], po[1], po[2], po[3]);
    }
}

__global__ __launch_bounds__(256) void recurrence4(const float* __restrict__ qT,
                                                   const float* __restrict__ k,
                                                   const float* __restrict__ vT,
                                                   const float* __restrict__ al,
                                                   const float* __restrict__ be,
                                                   const float* __restrict__ gram,
                                                   float* __restrict__ opart)
{
    extern __shared__ float osh[];   // [2][8][8][128] = 64 KB

    const int g   = blockIdx.x;   // 0..7
    const int bb  = blockIdx.y;   // 0..15
    const int tid = threadIdx.x;
    const int warp = tid >> 5, lane = tid & 31;
    const int i0 = g * 16 + warp * 2;
    const int i1 = i0 + 1;
    const int jb = lane * 4;

    const size_t bbase = (size_t)bb * T_ * C_;
    const size_t sbase = (size_t)bb * T_;
    const float* kg  = k + bbase;
    const float* qT0 = qT + bbase + (size_t)i0 * T_;
    const float* qT1 = qT + bbase + (size_t)i1 * T_;
    const float* vT0 = vT + bbase + (size_t)i0 * T_;
    const float* vT1 = vT + bbase + (size_t)i1 * T_;
    const float* ag = al + sbase;
    const float* bg = be + sbase;
    const float* gramb = gram + (size_t)bb * NCH * 8;
    float* op = opart + (size_t)g * M_ * C_ + bbase;

    float S0[4], S1[4];
#pragma unroll
    for (int jj = 0; jj < 4; ++jj) { S0[jj] = 0.0f; S1[jj] = 0.0f; }

    ChunkRegs RA, RB;
    load_chunk(0, kg, qT0, qT1, vT0, vT1, ag, bg, gramb, jb, RA);

    const int fst = tid >> 5;            // flush step 0..7
    const int fc4 = (tid & 31) * 4;      // flush col group

#pragma unroll 1
    for (int tc = 0; tc < NCH; tc += 2) {
        const int buf = (tc >> 1) & 1;
        chunk_body(tc,   buf, 0, true,          S0, S1, RA, RB, kg, qT0, qT1, vT0, vT1, ag, bg, gramb, jb, warp, lane, osh);
        chunk_body(tc+1, buf, 1, (tc+2) < NCH,  S0, S1, RB, RA, kg, qT0, qT1, vT0, vT1, ag, bg, gramb, jb, warp, lane, osh);
        __syncthreads();   // one barrier per 2 chunks

        // flush: 8 steps x 128 cols, 256 threads -> 1 float4 slot each
        const float* base = &osh[((size_t)buf*8 + fst)*8*C_];
        float4 acc = *(const float4*)(base + fc4);
#pragma unroll
        for (int w = 1; w < 8; ++w) {
            const float4 p = *(const float4*)(base + w*C_ + fc4);
            acc.x += p.x; acc.y += p.y; acc.z += p.z; acc.w += p.w;
        }
        *(float4*)(op + ((size_t)tc*LCH + fst) * C_ + fc4) = acc;
    }
}

// =============================================================================
// combine: o = (sum over groups of opart) * gate -> bf16 hi/lo split
// =============================================================================
__global__ __launch_bounds__(256) void combine_split(const float* __restrict__ opart,
                                                     const float* __restrict__ gate,
                                                     bf16* __restrict__ oh,
                                                     bf16* __restrict__ ol)
{
    const size_t idx = ((size_t)blockIdx.x * 256 + threadIdx.x) * 4;
    float4 s = make_float4(0.f, 0.f, 0.f, 0.f);
#pragma unroll
    for (int g = 0; g < GROUPS; ++g) {
        float4 p = *(const float4*)(opart + (size_t)g * M_ * C_ + idx);
        s.x += p.x; s.y += p.y; s.z += p.z; s.w += p.w;
    }
    float4 gt = *(const float4*)(gate + idx);
    s.x *= gt.x; s.y *= gt.y; s.z *= gt.z; s.w *= gt.w;

    bf16 h0 = __float2bfloat16_rn(s.x);
    bf16 h1 = __float2bfloat16_rn(s.y);
    bf16 h2 = __float2bfloat16_rn(s.z);
    bf16 h3 = __float2bfloat16_rn(s.w);
    bf16 l0 = __float2bfloat16_rn(s.x - __bfloat162float(h0));
    bf16 l1 = __float2bfloat16_rn(s.y - __bfloat162float(h1));
    bf16 l2 = __float2bfloat16_rn(s.z - __bfloat162float(h2));
    bf16 l3 = __float2bfloat16_rn(s.w - __bfloat162float(h3));
    __nv_bfloat162* H = (__nv_bfloat162*)(oh + idx);
    __nv_bfloat162* L = (__nv_bfloat162*)(ol + idx);
    H[0] = __nv_bfloat162(h0, h1); H[1] = __nv_bfloat162(h2, h3);
    L[0] = __nv_bfloat162(l0, l1); L[1] = __nv_bfloat162(l2, l3);
}

// =============================================================================
extern "C" void kernel_launch(void* const* d_in, const int* in_sizes, int n_in,
                              void* d_out, int out_size)
{
    const float* x  = (const float*)d_in[0];
    const float* Wq = (const float*)d_in[1];
    const float* bq = (const float*)d_in[2];
    const float* Wk = (const float*)d_in[3];
    const float* bk = (const float*)d_in[4];
    const float* Wv = (const float*)d_in[5];
    const float* bv = (const float*)d_in[6];
    const float* Wa = (const float*)d_in[7];
    const float* ba = (const float*)d_in[8];
    const float* Wb = (const float*)d_in[9];
    const float* bb = (const float*)d_in[10];
    const float* Wg = (const float*)d_in[11];
    const float* bg = (const float*)d_in[12];
    const float* Wo = (const float*)d_in[13];
    const float* bo = (const float*)d_in[14];
    float* out = (float*)d_out;

    float *q, *k, *v, *g, *qT, *vT, *a, *b, *op, *gram;
    bf16 *xh, *xl, *oh, *ol;
    bf16 *wqh, *wql, *wkh, *wkl, *wvh, *wvl, *wgh, *wgl, *woh, *wol;
    cudaGetSymbolAddress((void**)&q,  g_q);
    cudaGetSymbolAddress((void**)&k,  g_k);
    cudaGetSymbolAddress((void**)&v,  g_v);
    cudaGetSymbolAddress((void**)&g,  g_g);
    cudaGetSymbolAddress((void**)&qT, g_qT);
    cudaGetSymbolAddress((void**)&vT, g_vT);
    cudaGetSymbolAddress((void**)&a,  g_a);
    cudaGetSymbolAddress((void**)&b,  g_b);
    cudaGetSymbolAddress((void**)&op, g_opart);
    cudaGetSymbolAddress((void**)&gram, g_gram);
    cudaGetSymbolAddress((void**)&xh, g_xh);
    cudaGetSymbolAddress((void**)&xl, g_xl);
    cudaGetSymbolAddress((void**)&oh, g_oh);
    cudaGetSymbolAddress((void**)&ol, g_ol);
    cudaGetSymbolAddress((void**)&wqh, g_wqh); cudaGetSymbolAddress((void**)&wql, g_wql);
    cudaGetSymbolAddress((void**)&wkh, g_wkh); cudaGetSymbolAddress((void**)&wkl, g_wkl);
    cudaGetSymbolAddress((void**)&wvh, g_wvh); cudaGetSymbolAddress((void**)&wvl, g_wvl);
    cudaGetSymbolAddress((void**)&wgh, g_wgh); cudaGetSymbolAddress((void**)&wgl, g_wgl);
    cudaGetSymbolAddress((void**)&woh, g_woh); cudaGetSymbolAddress((void**)&wol, g_wol);

    const dim3 blk(256);
    const int OSH = 2*8*8*C_*4;   // 64 KB dynamic smem for recurrence

    cudaFuncSetAttribute(recurrence4, cudaFuncAttributeMaxDynamicSharedMemorySize, OSH);

    // (0) fused prep: alpha/beta + x split + 5 weight splits
    fused_prep<<<M_/8 + 5*128, blk>>>(x, Wa, ba, Wb, bb, a, b, xh, xl,
                                      Wq, Wk, Wv, Wg, Wo,
                                      wqh, wql, wkh, wkl, wvh, wvl,
                                      wgh, wgl, woh, wol);

    // (1) fused 4-projection HMMA GEMM (k-norm + gate-sigmoid in epilogue)
    proj_gemm<<<dim3(4, M_/128), blk>>>(xh, xl,
                                        wqh, wql, wkh, wkl, wvh, wvl, wgh, wgl,
                                        bq, bk, bv, bg, q, k, v, g);

    // (2) gram + q/v transpose
    prep2<<<2048 + 16384, blk>>>(k, q, v, gram, qT, vT);

    // (3) chunked sequential recurrence (128 CTAs, 2 rows/warp)  <- profiled
    recurrence4<<<dim3(GROUPS, B_), blk, OSH>>>(qT, k, vT, a, b, gram, op);

    // (4) group-sum + gate -> bf16 split
    combine_split<<<(M_*C_/4)/256, blk>>>(op, g, oh, ol);

    // (5) output projection (HMMA)
    out_gemm<<<dim3(D_/128, M_/128), blk>>>(oh, ol, woh, wol, bo, out);
}

// round 13
// speedup vs baseline: 1.0716x; 1.0014x over previous
#include <cuda_runtime.h>
#include <cuda_bf16.h>
#include <cstdint>

#define B_ 16
#define T_ 4096
#define D_ 1024
#define C_ 128
#define M_ (B_*T_)        // 65536 tokens
#define GROUPS 8          // row-groups (16 rows each; 2 rows per warp)
#define LCH 4             // chunk length inside recurrence
#define NCH (T_/LCH)      // 1024 chunks per sequence

typedef __nv_bfloat16 bf16;

// ---------------- scratch (static device globals; no allocation) -------------
__device__ float g_q[(size_t)M_*C_];
__device__ float g_k[(size_t)M_*C_];
__device__ float g_v[(size_t)M_*C_];
__device__ float g_g[(size_t)M_*C_];
__device__ float g_qT[(size_t)M_*C_];   // [B][C][T]
__device__ float g_vT[(size_t)M_*C_];   // [B][C][T]
__device__ float g_a[M_];
__device__ float g_b[M_];
__device__ float g_opart[(size_t)GROUPS*M_*C_];
__device__ float g_gram[(size_t)B_*NCH*8];

__device__ bf16 g_xh[(size_t)M_*D_];
__device__ bf16 g_xl[(size_t)M_*D_];
__device__ bf16 g_oh[(size_t)M_*C_];
__device__ bf16 g_ol[(size_t)M_*C_];
__device__ bf16 g_wqh[C_*D_], g_wql[C_*D_];
__device__ bf16 g_wkh[C_*D_], g_wkl[C_*D_];
__device__ bf16 g_wvh[C_*D_], g_wvl[C_*D_];
__device__ bf16 g_wgh[C_*D_], g_wgl[C_*D_];
__device__ bf16 g_woh[D_*C_], g_wol[D_*C_];

__device__ __forceinline__ float sigmoidf_(float x) { return 1.0f / (1.0f + expf(-x)); }

// =============================================================================
// fused_prep: blocks [0, M_/8)            -> alpha/beta + x hi/lo split
//             blocks [M_/8, M_/8 + 640)   -> weight hi/lo splits (5 matrices)
// =============================================================================
__global__ __launch_bounds__(256) void fused_prep(
    const float* __restrict__ x,
    const float* __restrict__ Wa, const float* __restrict__ ba,
    const float* __restrict__ Wb, const float* __restrict__ bb,
    float* __restrict__ a_out, float* __restrict__ b_out,
    bf16* __restrict__ xh, bf16* __restrict__ xl,
    const float* Wq, const float* Wk, const float* Wv, const float* Wg, const float* Wo,
    bf16* wqh, bf16* wql, bf16* wkh, bf16* wkl, bf16* wvh, bf16* wvl,
    bf16* wgh, bf16* wgl, bf16* woh, bf16* wol)
{
    const int tid = threadIdx.x;
    constexpr int NAB = M_/8;

    if (blockIdx.x >= NAB) {
        const int widx = blockIdx.x - NAB;
        const int mat  = widx >> 7;
        const float* in; bf16 *hi, *lo;
        if      (mat == 0) { in = Wq; hi = wqh; lo = wql; }
        else if (mat == 1) { in = Wk; hi = wkh; lo = wkl; }
        else if (mat == 2) { in = Wv; hi = wvh; lo = wvl; }
        else if (mat == 3) { in = Wg; hi = wgh; lo = wgl; }
        else               { in = Wo; hi = woh; lo = wol; }
        const int i = (widx & 127) * 256 + tid;
        float4 xv = *(const float4*)(in + (size_t)i * 4);
        bf16 h0 = __float2bfloat16_rn(xv.x);
        bf16 h1 = __float2bfloat16_rn(xv.y);
        bf16 h2 = __float2bfloat16_rn(xv.z);
        bf16 h3 = __float2bfloat16_rn(xv.w);
        bf16 l0 = __float2bfloat16_rn(xv.x - __bfloat162float(h0));
        bf16 l1 = __float2bfloat16_rn(xv.y - __bfloat162float(h1));
        bf16 l2 = __float2bfloat16_rn(xv.z - __bfloat162float(h2));
        bf16 l3 = __float2bfloat16_rn(xv.w - __bfloat162float(h3));
        __nv_bfloat162* H = (__nv_bfloat162*)(hi + (size_t)i * 4);
        __nv_bfloat162* L = (__nv_bfloat162*)(lo + (size_t)i * 4);
        H[0] = __nv_bfloat162(h0, h1); H[1] = __nv_bfloat162(h2, h3);
        L[0] = __nv_bfloat162(l0, l1); L[1] = __nv_bfloat162(l2, l3);
        return;
    }

    __shared__ __align__(16) float sWa[D_];
    __shared__ __align__(16) float sWb[D_];
    for (int i = tid; i < D_; i += 256) { sWa[i] = Wa[i]; sWb[i] = Wb[i]; }
    __syncthreads();

    const int warp = tid >> 5, lane = tid & 31;
    const int tok  = blockIdx.x * 8 + warp;
    const size_t base = (size_t)tok * D_;
    const float* xr = x + base;

    float da = 0.0f, db = 0.0f;
#pragma unroll
    for (int j = 0; j < 8; ++j) {
        const int off = j*128 + lane*4;
        float4 xv = *(const float4*)(xr  + off);
        float4 wa = *(const float4*)(sWa + off);
        float4 wb = *(const float4*)(sWb + off);
        da += xv.x*wa.x + xv.y*wa.y + xv.z*wa.z + xv.w*wa.w;
        db += xv.x*wb.x + xv.y*wb.y + xv.z*wb.z + xv.w*wb.w;

        bf16 h0 = __float2bfloat16_rn(xv.x);
        bf16 h1 = __float2bfloat16_rn(xv.y);
        bf16 h2 = __float2bfloat16_rn(xv.z);
        bf16 h3 = __float2bfloat16_rn(xv.w);
        bf16 l0 = __float2bfloat16_rn(xv.x - __bfloat162float(h0));
        bf16 l1 = __float2bfloat16_rn(xv.y - __bfloat162float(h1));
        bf16 l2 = __float2bfloat16_rn(xv.z - __bfloat162float(h2));
        bf16 l3 = __float2bfloat16_rn(xv.w - __bfloat162float(h3));
        __nv_bfloat162* H = (__nv_bfloat162*)(xh + base + off);
        __nv_bfloat162* L = (__nv_bfloat162*)(xl + base + off);
        H[0] = __nv_bfloat162(h0, h1); H[1] = __nv_bfloat162(h2, h3);
        L[0] = __nv_bfloat162(l0, l1); L[1] = __nv_bfloat162(l2, l3);
    }
#pragma unroll
    for (int off = 16; off > 0; off >>= 1) {
        da += __shfl_xor_sync(0xffffffffu, da, off);
        db += __shfl_xor_sync(0xffffffffu, db, off);
    }
    if (lane == 0) {
        a_out[tok] = sigmoidf_(da + ba[0]);
        b_out[tok] = sigmoidf_(db + bb[0]);
    }
}

// =============================================================================
// Tensor-core NT GEMM core (HMMA mma.sync).
// =============================================================================
__device__ __forceinline__ void ldsm4(uint32_t& r0, uint32_t& r1,
                                      uint32_t& r2, uint32_t& r3, uint32_t a)
{
    asm volatile("ldmatrix.sync.aligned.m8n8.x4.shared.b16 {%0,%1,%2,%3}, [%4];"
                 : "=r"(r0), "=r"(r1), "=r"(r2), "=r"(r3) : "r"(a));
}

__device__ __forceinline__ void mma16816(float c[4], const uint32_t a[4], const uint32_t b[2])
{
    asm volatile("mma.sync.aligned.m16n8k16.row.col.f32.bf16.bf16.f32 "
                 "{%0,%1,%2,%3}, {%4,%5,%6,%7}, {%8,%9}, {%0,%1,%2,%3};"
                 : "+f"(c[0]), "+f"(c[1]), "+f"(c[2]), "+f"(c[3])
                 : "r"(a[0]), "r"(a[1]), "r"(a[2]), "r"(a[3]), "r"(b[0]), "r"(b[1]));
}

template<int KDIM>
__device__ __forceinline__ void mma_loop(const bf16* __restrict__ A0,
                                         const bf16* __restrict__ A1,
                                         const bf16* __restrict__ A2,
                                         const bf16* __restrict__ B0,
                                         const bf16* __restrict__ B1,
                                         const bf16* __restrict__ B2,
                                         int m0, uint4* sA, uint4* sB,
                                         float acc[4][4][4])
{
    constexpr int KIT = KDIM / 32;
    constexpr int TOT = 3 * KIT;
    const int tid  = threadIdx.x;
    const int lane = tid & 31, warp = tid >> 5;
    const int wm = warp & 1, wn = warp >> 1;

    const int r0_ = tid >> 2,        u_ = tid & 3;
    const int r1_ = 64 + (tid >> 2);
    const int st0 = r0_ * 4 + (u_ ^ ((r0_ >> 1) & 3));
    const int st1 = r1_ * 4 + (u_ ^ ((r1_ >> 1) & 3));

    const uint32_t saB = (uint32_t)__cvta_generic_to_shared(sA);
    const uint32_t sbB = (uint32_t)__cvta_generic_to_shared(sB);

    uint4 ra0, ra1, rb0, rb1;
    {
        ra0 = *(const uint4*)(A0 + (size_t)(m0 + r0_) * KDIM + u_ * 8);
        ra1 = *(const uint4*)(A0 + (size_t)(m0 + r1_) * KDIM + u_ * 8);
        rb0 = *(const uint4*)(B0 + (size_t)r0_ * KDIM + u_ * 8);
        rb1 = *(const uint4*)(B0 + (size_t)r1_ * KDIM + u_ * 8);
    }

#pragma unroll 1
    for (int it = 0; it < TOT; ++it) {
        const int buf = it & 1;
        sA[buf * 512 + st0] = ra0; sA[buf * 512 + st1] = ra1;
        sB[buf * 512 + st0] = rb0; sB[buf * 512 + st1] = rb1;
        __syncthreads();

        if (it + 1 < TOT) {
            const int nit = it + 1;
            const int p = nit / KIT;
            const int kk = (nit - p * KIT) * 32;
            const bf16* Ap = (p == 0) ? A0 : (p == 1) ? A1 : A2;
            const bf16* Bp = (p == 0) ? B0 : (p == 1) ? B1 : B2;
            ra0 = *(const uint4*)(Ap + (size_t)(m0 + r0_) * KDIM + kk + u_ * 8);
            ra1 = *(const uint4*)(Ap + (size_t)(m0 + r1_) * KDIM + kk + u_ * 8);
            rb0 = *(const uint4*)(Bp + (size_t)r0_ * KDIM + kk + u_ * 8);
            rb1 = *(const uint4*)(Bp + (size_t)r1_ * KDIM + kk + u_ * 8);
        }

        const uint32_t aBase = saB + buf * 8192;
        const uint32_t bBase = sbB + buf * 8192;
#pragma unroll
        for (int ks = 0; ks < 2; ++ks) {
            uint32_t af[4][4], bfr[4][2];
#pragma unroll
            for (int mt = 0; mt < 4; ++mt) {
                const int row = wm * 64 + mt * 16 + (lane & 15);
                const int u = ks * 2 + (lane >> 4);
                ldsm4(af[mt][0], af[mt][1], af[mt][2], af[mt][3],
                      aBase + (uint32_t)((row * 4 + (u ^ ((row >> 1) & 3))) * 16));
            }
#pragma unroll
            for (int j = 0; j < 2; ++j) {
                const int gq = lane >> 3;
                const int n = wn * 32 + j * 16 + ((gq >> 1) << 3) + (lane & 7);
                const int u = ks * 2 + (gq & 1);
                uint32_t t0, t1, t2, t3;
                ldsm4(t0, t1, t2, t3,
                      bBase + (uint32_t)((n * 4 + (u ^ ((n >> 1) & 3))) * 16));
                bfr[j*2][0] = t0; bfr[j*2][1] = t1;
                bfr[j*2+1][0] = t2; bfr[j*2+1][1] = t3;
            }
#pragma unroll
            for (int mt = 0; mt < 4; ++mt)
#pragma unroll
                for (int nt = 0; nt < 4; ++nt)
                    mma16816(acc[mt][nt], af[mt], bfr[nt]);
        }
    }
}

// =============================================================================
// Fused 4-projection GEMM (HMMA).
// =============================================================================
__global__ __launch_bounds__(256, 2) void proj_gemm(
    const bf16* __restrict__ xh, const bf16* __restrict__ xl,
    const bf16* wqh, const bf16* wql, const bf16* wkh, const bf16* wkl,
    const bf16* wvh, const bf16* wvl, const bf16* wgh, const bf16* wgl,
    const float* bq, const float* bk, const float* bv, const float* bg,
    float* outq, float* outk, float* outv, float* outg)
{
    __shared__ uint4 sA[1024];
    __shared__ uint4 sB[1024];
    __shared__ float snorm[4][128];

    const int proj = blockIdx.x;
    const int m0 = blockIdx.y * 128;
    const bf16 *Bh, *Bl; const float* bias; float* C;
    if      (proj == 0) { Bh = wqh; Bl = wql; bias = bq; C = outq; }
    else if (proj == 1) { Bh = wkh; Bl = wkl; bias = bk; C = outk; }
    else if (proj == 2) { Bh = wvh; Bl = wvl; bias = bv; C = outv; }
    else                { Bh = wgh; Bl = wgl; bias = bg; C = outg; }

    float acc[4][4][4];
#pragma unroll
    for (int mt = 0; mt < 4; ++mt)
#pragma unroll
        for (int nt = 0; nt < 4; ++nt)
#pragma unroll
            for (int c = 0; c < 4; ++c) acc[mt][nt][c] = 0.0f;

    mma_loop<D_>(xh, xh, xl, Bh, Bl, Bh, m0, sA, sB, acc);

    const int lane = threadIdx.x & 31, warp = threadIdx.x >> 5;
    const int wm = warp & 1, wn = warp >> 1;

#pragma unroll
    for (int nt = 0; nt < 4; ++nt) {
        const int col = wn * 32 + nt * 8 + (lane & 3) * 2;
        const float b0 = bias[col], b1 = bias[col + 1];
#pragma unroll
        for (int mt = 0; mt < 4; ++mt) {
            acc[mt][nt][0] += b0; acc[mt][nt][1] += b1;
            acc[mt][nt][2] += b0; acc[mt][nt][3] += b1;
        }
    }

    if (proj == 3) {
#pragma unroll
        for (int mt = 0; mt < 4; ++mt)
#pragma unroll
            for (int nt = 0; nt < 4; ++nt)
#pragma unroll
                for (int c = 0; c < 4; ++c)
                    acc[mt][nt][c] = sigmoidf_(acc[mt][nt][c]);
    }

    if (proj == 1) {
#pragma unroll
        for (int mt = 0; mt < 4; ++mt)
#pragma unroll
            for (int h = 0; h < 2; ++h) {
                float ss = 0.0f;
#pragma unroll
                for (int nt = 0; nt < 4; ++nt) {
                    ss += acc[mt][nt][2*h] * acc[mt][nt][2*h];
                    ss += acc[mt][nt][2*h+1] * acc[mt][nt][2*h+1];
                }
                ss += __shfl_xor_sync(0xffffffffu, ss, 1);
                ss += __shfl_xor_sync(0xffffffffu, ss, 2);
                if ((lane & 3) == 0)
                    snorm[wn][wm*64 + mt*16 + h*8 + (lane >> 2)] = ss;
            }
        __syncthreads();
#pragma unroll
        for (int mt = 0; mt < 4; ++mt)
#pragma unroll
            for (int h = 0; h < 2; ++h) {
                const int row = wm*64 + mt*16 + h*8 + (lane >> 2);
                const float s = snorm[0][row] + snorm[1][row] + snorm[2][row] + snorm[3][row];
                const float inv = 1.0f / fmaxf(sqrtf(s), 1e-12f);
#pragma unroll
                for (int nt = 0; nt < 4; ++nt) {
                    acc[mt][nt][2*h]   *= inv;
                    acc[mt][nt][2*h+1] *= inv;
                }
            }
    }

#pragma unroll
    for (int mt = 0; mt < 4; ++mt) {
        const int r = m0 + wm*64 + mt*16 + (lane >> 2);
#pragma unroll
        for (int nt = 0; nt < 4; ++nt) {
            const int col = wn*32 + nt*8 + (lane & 3)*2;
            *(float2*)(C + (size_t)r * C_ + col)       = make_float2(acc[mt][nt][0], acc[mt][nt][1]);
            *(float2*)(C + (size_t)(r+8) * C_ + col)   = make_float2(acc[mt][nt][2], acc[mt][nt][3]);
        }
    }
}

// =============================================================================
// Output GEMM (HMMA).
// =============================================================================
__global__ __launch_bounds__(256, 2) void out_gemm(
    const bf16* __restrict__ oh, const bf16* __restrict__ ol,
    const bf16* __restrict__ woh, const bf16* __restrict__ wol,
    const float* __restrict__ bo, float* __restrict__ out)
{
    __shared__ uint4 sA[1024];
    __shared__ uint4 sB[1024];

    const int n0 = blockIdx.x * 128;
    const int m0 = blockIdx.y * 128;
    const bf16* Bh = woh + (size_t)n0 * C_;
    const bf16* Bl = wol + (size_t)n0 * C_;

    float acc[4][4][4];
#pragma unroll
    for (int mt = 0; mt < 4; ++mt)
#pragma unroll
        for (int nt = 0; nt < 4; ++nt)
#pragma unroll
            for (int c = 0; c < 4; ++c) acc[mt][nt][c] = 0.0f;

    mma_loop<C_>(oh, oh, ol, Bh, Bl, Bh, m0, sA, sB, acc);

    const int lane = threadIdx.x & 31, warp = threadIdx.x >> 5;
    const int wm = warp & 1, wn = warp >> 1;

#pragma unroll
    for (int mt = 0; mt < 4; ++mt) {
        const int r = m0 + wm*64 + mt*16 + (lane >> 2);
#pragma unroll
        for (int nt = 0; nt < 4; ++nt) {
            const int col = n0 + wn*32 + nt*8 + (lane & 3)*2;
            const float b0 = bo[col], b1 = bo[col + 1];
            *(float2*)(out + (size_t)r * D_ + col)
                = make_float2(acc[mt][nt][0] + b0, acc[mt][nt][1] + b1);
            *(float2*)(out + (size_t)(r+8) * D_ + col)
                = make_float2(acc[mt][nt][2] + b0, acc[mt][nt][3] + b1);
        }
    }
}

// =============================================================================
// prep2: blocks [0, 2048)          -> chunk Gram precompute (1 warp per chunk)
//        blocks [2048, 2048+16384) -> q/v transpose to [B][C][T]
// =============================================================================
__global__ __launch_bounds__(256) void prep2(const float* __restrict__ k,
                                             const float* __restrict__ q,
                                             const float* __restrict__ v,
                                             float* __restrict__ gram,
                                             float* __restrict__ qT,
                                             float* __restrict__ vT)
{
    const int tid = threadIdx.x;

    if (blockIdx.x < 2048) {
        const int warp = tid >> 5, lane = tid & 31;
        const int cid = blockIdx.x * 8 + warp;
        const int bb = cid >> 10, tc = cid & 1023;
        const float* kg = k + ((size_t)bb * T_ + (size_t)tc * LCH) * C_ + lane * 4;

        float4 k0 = *(const float4*)(kg + 0*C_);
        float4 k1 = *(const float4*)(kg + 1*C_);
        float4 k2 = *(const float4*)(kg + 2*C_);
        float4 k3 = *(const float4*)(kg + 3*C_);

        float G01 = k0.x*k1.x + k0.y*k1.y + k0.z*k1.z + k0.w*k1.w;
        float G02 = k0.x*k2.x + k0.y*k2.y + k0.z*k2.z + k0.w*k2.w;
        float G03 = k0.x*k3.x + k0.y*k3.y + k0.z*k3.z + k0.w*k3.w;
        float G12 = k1.x*k2.x + k1.y*k2.y + k1.z*k2.z + k1.w*k2.w;
        float G13 = k1.x*k3.x + k1.y*k3.y + k1.z*k3.z + k1.w*k3.w;
        float G23 = k2.x*k3.x + k2.y*k3.y + k2.z*k3.z + k2.w*k3.w;

#pragma unroll
        for (int off = 16; off > 0; off >>= 1) {
            G01 += __shfl_xor_sync(0xffffffffu, G01, off);
            G02 += __shfl_xor_sync(0xffffffffu, G02, off);
            G03 += __shfl_xor_sync(0xffffffffu, G03, off);
            G12 += __shfl_xor_sync(0xffffffffu, G12, off);
            G13 += __shfl_xor_sync(0xffffffffu, G13, off);
            G23 += __shfl_xor_sync(0xffffffffu, G23, off);
        }
        if (lane == 0) {
            float* gp = gram + (size_t)cid * 8;
            *(float4*)(gp)     = make_float4(G01, G02, G03, G12);
            *(float4*)(gp + 4) = make_float4(G13, G23, 0.0f, 0.0f);
        }
        return;
    }

    __shared__ float ts[32][33];
    const int tt = blockIdx.x - 2048;
    const int tensor = tt >> 13;
    const int rem = tt & 8191;
    const int bb = rem >> 9;
    const int tile = rem & 511;
    const int ct = tile >> 7;
    const int tk = tile & 127;

    const float* src = tensor ? v : q;
    float* dst = tensor ? vT : qT;
    const size_t sbase = (size_t)bb * T_ * C_;

    const int ty = tid >> 5, lane = tid & 31;
#pragma unroll
    for (int r = 0; r < 4; ++r) {
        const int row = tk*32 + ty + r*8;
        ts[ty + r*8][lane] = src[sbase + (size_t)row * C_ + ct*32 + lane];
    }
    __syncthreads();
#pragma unroll
    for (int r = 0; r < 4; ++r) {
        const int c = ct*32 + ty + r*8;
        dst[sbase + (size_t)c * T_ + tk*32 + lane] = ts[lane][ty + r*8];
    }
}

// =============================================================================
// Chunked (L=4) gated delta-rule recurrence, GROUPS=8, TWO ROWS PER WARP.
// Grid (8, 16) = 128 CTAs, 1/SM. Warp w owns rows i0 = g*16+2w, i1 = i0+1;
// lane owns 4 cols of each row. po = q0*S0 + q1*S1 summed in registers ->
// per-warp k/STS/LDS traffic amortized over 2 rows (total L1 traffic halved).
// =============================================================================
struct ChunkRegs {
    float k[LCH][4];
    float q0[LCH], q1[LCH], v0[LCH], v1[LCH], a[LCH], b[LCH];
    float G[6];
};

__device__ __forceinline__ float red32(float x) {
    x += __shfl_xor_sync(0xffffffffu, x, 1);
    x += __shfl_xor_sync(0xffffffffu, x, 2);
    x += __shfl_xor_sync(0xffffffffu, x, 4);
    x += __shfl_xor_sync(0xffffffffu, x, 8);
    x += __shfl_xor_sync(0xffffffffu, x, 16);
    return x;
}

__device__ __forceinline__ void load_chunk(int tcN,
                                           const float* __restrict__ kg,
                                           const float* __restrict__ qT0,
                                           const float* __restrict__ qT1,
                                           const float* __restrict__ vT0,
                                           const float* __restrict__ vT1,
                                           const float* __restrict__ ag,
                                           const float* __restrict__ bg,
                                           const float* __restrict__ gramb,
                                           int jb, ChunkRegs& R)
{
#pragma unroll
    for (int t4 = 0; t4 < LCH; ++t4) {
        const size_t off = ((size_t)tcN*LCH + t4) * C_;
        float4 kx = *(const float4*)(kg + off + jb);
        R.k[t4][0]=kx.x; R.k[t4][1]=kx.y; R.k[t4][2]=kx.z; R.k[t4][3]=kx.w;
    }
    float4 q4 = *(const float4*)(qT0 + tcN*LCH);
    R.q0[0]=q4.x; R.q0[1]=q4.y; R.q0[2]=q4.z; R.q0[3]=q4.w;
    q4 = *(const float4*)(qT1 + tcN*LCH);
    R.q1[0]=q4.x; R.q1[1]=q4.y; R.q1[2]=q4.z; R.q1[3]=q4.w;
    float4 v4 = *(const float4*)(vT0 + tcN*LCH);
    R.v0[0]=v4.x; R.v0[1]=v4.y; R.v0[2]=v4.z; R.v0[3]=v4.w;
    v4 = *(const float4*)(vT1 + tcN*LCH);
    R.v1[0]=v4.x; R.v1[1]=v4.y; R.v1[2]=v4.z; R.v1[3]=v4.w;
    float4 a4 = *(const float4*)(ag + tcN*LCH);
    float4 b4 = *(const float4*)(bg + tcN*LCH);
    R.a[0]=a4.x; R.a[1]=a4.y; R.a[2]=a4.z; R.a[3]=a4.w;
    R.b[0]=b4.x; R.b[1]=b4.y; R.b[2]=b4.z; R.b[3]=b4.w;
    float4 ga = *(const float4*)(gramb + (size_t)tcN * 8);
    float4 gb = *(const float4*)(gramb + (size_t)tcN * 8 + 4);
    R.G[0]=ga.x; R.G[1]=ga.y; R.G[2]=ga.z; R.G[3]=ga.w;
    R.G[4]=gb.x; R.G[5]=gb.y;
}

// exact per-row scalar recursion (shared a,b,G; row-specific m,v)
__device__ __forceinline__ void row_recursion(const ChunkRegs& cur,
                                              const float m[LCH], const float* vv,
                                              float cc[LCH])
{
    const float a0=cur.a[0], a1=cur.a[1], a2=cur.a[2], a3=cur.a[3];
    const float G01=cur.G[0], G02=cur.G[1], G03=cur.G[2];
    const float G12=cur.G[3], G13=cur.G[4], G23=cur.G[5];
    const float u0 = m[0];
    cc[0] = cur.b[0] * (vv[0] - a0*u0);
    const float u1 = a0*m[1] + cc[0]*G01;
    cc[1] = cur.b[1] * (vv[1] - a1*u1);
    const float a01 = a0*a1;
    const float u2 = a01*m[2] + a1*cc[0]*G02 + cc[1]*G12;
    cc[2] = cur.b[2] * (vv[2] - a2*u2);
    const float u3 = a01*a2*m[3] + a1*a2*cc[0]*G03 + a2*cc[1]*G13 + cc[2]*G23;
    cc[3] = cur.b[3] * (vv[3] - a3*u3);
}

// osh layout: [buf(2)][step(8)][warp(8)][col(128)]
__device__ __forceinline__ void chunk_body(int tc, int buf, int cig, bool pf,
                                           float S0[4], float S1[4],
                                           ChunkRegs& cur, ChunkRegs& nxt,
                                           const float* __restrict__ kg,
                                           const float* __restrict__ qT0,
                                           const float* __restrict__ qT1,
                                           const float* __restrict__ vT0,
                                           const float* __restrict__ vT1,
                                           const float* __restrict__ ag,
                                           const float* __restrict__ bg,
                                           const float* __restrict__ gramb,
                                           int jb, int warp, int lane,
                                           float* __restrict__ osh)
{
    // --- phase 1: m partials vs chunk-start S for both rows ---
    float m0[LCH], m1[LCH];
#pragma unroll
    for (int t4 = 0; t4 < LCH; ++t4) {
        float s0 = 0.0f, s1 = 0.0f;
#pragma unroll
        for (int jj = 0; jj < 4; ++jj) {
            s0 += S0[jj] * cur.k[t4][jj];
            s1 += S1[jj] * cur.k[t4][jj];
        }
        m0[t4] = s0; m1[t4] = s1;
    }

    if (pf) load_chunk(tc + 1, kg, qT0, qT1, vT0, vT1, ag, bg, gramb, jb, nxt);

    // --- 8 independent full-warp reductions ---
    m0[0]=red32(m0[0]); m0[1]=red32(m0[1]); m0[2]=red32(m0[2]); m0[3]=red32(m0[3]);
    m1[0]=red32(m1[0]); m1[1]=red32(m1[1]); m1[2]=red32(m1[2]); m1[3]=red32(m1[3]);

    // --- phase 2: exact scalar recursion per row ---
    float cc0[LCH], cc1[LCH];
    row_recursion(cur, m0, cur.v0, cc0);
    row_recursion(cur, m1, cur.v1, cc1);

    // --- phase 3: per-step register updates + register-summed o partials ---
#pragma unroll
    for (int t4 = 0; t4 < LCH; ++t4) {
        float po[4];
#pragma unroll
        for (int jj = 0; jj < 4; ++jj) {
            S0[jj] = cur.a[t4] * S0[jj] + cc0[t4] * cur.k[t4][jj];
            S1[jj] = cur.a[t4] * S1[jj] + cc1[t4] * cur.k[t4][jj];
            po[jj] = cur.q0[t4] * S0[jj] + cur.q1[t4] * S1[jj];
        }
        const int step = cig * LCH + t4;
        *(float4*)&osh[(((size_t)buf*8 + step)*8 + warp)*C_ + lane*4]
            = make_float4(po[0], po[1], po[2], po[3]);
    }
}

__global__ __launch_bounds__(256) void recurrence4(const float* __restrict__ qT,
                                                   const float* __restrict__ k,
                                                   const float* __restrict__ vT,
                                                   const float* __restrict__ al,
                                                   const float* __restrict__ be,
                                                   const float* __restrict__ gram,
                                                   float* __restrict__ opart)
{
    extern __shared__ float osh[];   // [2][8][8][128] = 64 KB

    const int g   = blockIdx.x;   // 0..7
    const int bb  = blockIdx.y;   // 0..15
    const int tid = threadIdx.x;
    const int warp = tid >> 5, lane = tid & 31;
    const int i0 = g * 16 + warp * 2;
    const int i1 = i0 + 1;
    const int jb = lane * 4;

    const size_t bbase = (size_t)bb * T_ * C_;
    const size_t sbase = (size_t)bb * T_;
    const float* kg  = k + bbase;
    const float* qT0 = qT + bbase + (size_t)i0 * T_;
    const float* qT1 = qT + bbase + (size_t)i1 * T_;
    const float* vT0 = vT + bbase + (size_t)i0 * T_;
    const float* vT1 = vT + bbase + (size_t)i1 * T_;
    const float* ag = al + sbase;
    const float* bg = be + sbase;
    const float* gramb = gram + (size_t)bb * NCH * 8;
    float* op = opart + (size_t)g * M_ * C_ + bbase;

    float S0[4], S1[4];
#pragma unroll
    for (int jj = 0; jj < 4; ++jj) { S0[jj] = 0.0f; S1[jj] = 0.0f; }

    ChunkRegs RA, RB;
    load_chunk(0, kg, qT0, qT1, vT0, vT1, ag, bg, gramb, jb, RA);

    const int fst = tid >> 5;            // flush step 0..7
    const int fc4 = (tid & 31) * 4;      // flush col group

#pragma unroll 1
    for (int tc = 0; tc < NCH; tc += 2) {
        const int buf = (tc >> 1) & 1;
        chunk_body(tc,   buf, 0, true,          S0, S1, RA, RB, kg, qT0, qT1, vT0, vT1, ag, bg, gramb, jb, warp, lane, osh);
        chunk_body(tc+1, buf, 1, (tc+2) < NCH,  S0, S1, RB, RA, kg, qT0, qT1, vT0, vT1, ag, bg, gramb, jb, warp, lane, osh);
        __syncthreads();   // one barrier per 2 chunks

        // flush: 8 steps x 128 cols, 256 threads -> 1 float4 slot each
        const float* base = &osh[((size_t)buf*8 + fst)*8*C_];
        float4 acc = *(const float4*)(base + fc4);
#pragma unroll
        for (int w = 1; w < 8; ++w) {
            const float4 p = *(const float4*)(base + w*C_ + fc4);
            acc.x += p.x; acc.y += p.y; acc.z += p.z; acc.w += p.w;
        }
        *(float4*)(op + ((size_t)tc*LCH + fst) * C_ + fc4) = acc;
    }
}

// =============================================================================
// combine: o = (sum over groups of opart) * gate -> bf16 hi/lo split
// =============================================================================
__global__ __launch_bounds__(256) void combine_split(const float* __restrict__ opart,
                                                     const float* __restrict__ gate,
                                                     bf16* __restrict__ oh,
                                                     bf16* __restrict__ ol)
{
    const size_t idx = ((size_t)blockIdx.x * 256 + threadIdx.x) * 4;
    float4 s = make_float4(0.f, 0.f, 0.f, 0.f);
#pragma unroll
    for (int g = 0; g < GROUPS; ++g) {
        float4 p = *(const float4*)(opart + (size_t)g * M_ * C_ + idx);
        s.x += p.x; s.y += p.y; s.z += p.z; s.w += p.w;
    }
    float4 gt = *(const float4*)(gate + idx);
    s.x *= gt.x; s.y *= gt.y; s.z *= gt.z; s.w *= gt.w;

    bf16 h0 = __float2bfloat16_rn(s.x);
    bf16 h1 = __float2bfloat16_rn(s.y);
    bf16 h2 = __float2bfloat16_rn(s.z);
    bf16 h3 = __float2bfloat16_rn(s.w);
    bf16 l0 = __float2bfloat16_rn(s.x - __bfloat162float(h0));
    bf16 l1 = __float2bfloat16_rn(s.y - __bfloat162float(h1));
    bf16 l2 = __float2bfloat16_rn(s.z - __bfloat162float(h2));
    bf16 l3 = __float2bfloat16_rn(s.w - __bfloat162float(h3));
    __nv_bfloat162* H = (__nv_bfloat162*)(oh + idx);
    __nv_bfloat162* L = (__nv_bfloat162*)(ol + idx);
    H[0] = __nv_bfloat162(h0, h1); H[1] = __nv_bfloat162(h2, h3);
    L[0] = __nv_bfloat162(l0, l1); L[1] = __nv_bfloat162(l2, l3);
}

// =============================================================================
extern "C" void kernel_launch(void* const* d_in, const int* in_sizes, int n_in,
                              void* d_out, int out_size)
{
    const float* x  = (const float*)d_in[0];
    const float* Wq = (const float*)d_in[1];
    const float* bq = (const float*)d_in[2];
    const float* Wk = (const float*)d_in[3];
    const float* bk = (const float*)d_in[4];
    const float* Wv = (const float*)d_in[5];
    const float* bv = (const float*)d_in[6];
    const float* Wa = (const float*)d_in[7];
    const float* ba = (const float*)d_in[8];
    const float* Wb = (const float*)d_in[9];
    const float* bb = (const float*)d_in[10];
    const float* Wg = (const float*)d_in[11];
    const float* bg = (const float*)d_in[12];
    const float* Wo = (const float*)d_in[13];
    const float* bo = (const float*)d_in[14];
    float* out = (float*)d_out;

    float *q, *k, *v, *g, *qT, *vT, *a, *b, *op, *gram;
    bf16 *xh, *xl, *oh, *ol;
    bf16 *wqh, *wql, *wkh, *wkl, *wvh, *wvl, *wgh, *wgl, *woh, *wol;
    cudaGetSymbolAddress((void**)&q,  g_q);
    cudaGetSymbolAddress((void**)&k,  g_k);
    cudaGetSymbolAddress((void**)&v,  g_v);
    cudaGetSymbolAddress((void**)&g,  g_g);
    cudaGetSymbolAddress((void**)&qT, g_qT);
    cudaGetSymbolAddress((void**)&vT, g_vT);
    cudaGetSymbolAddress((void**)&a,  g_a);
    cudaGetSymbolAddress((void**)&b,  g_b);
    cudaGetSymbolAddress((void**)&op, g_opart);
    cudaGetSymbolAddress((void**)&gram, g_gram);
    cudaGetSymbolAddress((void**)&xh, g_xh);
    cudaGetSymbolAddress((void**)&xl, g_xl);
    cudaGetSymbolAddress((void**)&oh, g_oh);
    cudaGetSymbolAddress((void**)&ol, g_ol);
    cudaGetSymbolAddress((void**)&wqh, g_wqh); cudaGetSymbolAddress((void**)&wql, g_wql);
    cudaGetSymbolAddress((void**)&wkh, g_wkh); cudaGetSymbolAddress((void**)&wkl, g_wkl);
    cudaGetSymbolAddress((void**)&wvh, g_wvh); cudaGetSymbolAddress((void**)&wvl, g_wvl);
    cudaGetSymbolAddress((void**)&wgh, g_wgh); cudaGetSymbolAddress((void**)&wgl, g_wgl);
    cudaGetSymbolAddress((void**)&woh, g_woh); cudaGetSymbolAddress((void**)&wol, g_wol);

    const dim3 blk(256);
    const int OSH = 2*8*8*C_*4;   // 64 KB dynamic smem for recurrence

    cudaFuncSetAttribute(recurrence4, cudaFuncAttributeMaxDynamicSharedMemorySize, OSH);

    // (0) fused prep: alpha/beta + x split + 5 weight splits
    fused_prep<<<M_/8 + 5*128, blk>>>(x, Wa, ba, Wb, bb, a, b, xh, xl,
                                      Wq, Wk, Wv, Wg, Wo,
                                      wqh, wql, wkh, wkl, wvh, wvl,
                                      wgh, wgl, woh, wol);

    // (1) fused 4-projection HMMA GEMM (k-norm + gate-sigmoid in epilogue)
    proj_gemm<<<dim3(4, M_/128), blk>>>(xh, xl,
                                        wqh, wql, wkh, wkl, wvh, wvl, wgh, wgl,
                                        bq, bk, bv, bg, q, k, v, g);

    // (2) gram + q/v transpose
    prep2<<<2048 + 16384, blk>>>(k, q, v, gram, qT, vT);

    // (3) chunked sequential recurrence (128 CTAs, 2 rows/warp)  <- profiled
    recurrence4<<<dim3(GROUPS, B_), blk, OSH>>>(qT, k, vT, a, b, gram, op);

    // (4) group-sum + gate -> bf16 split
    combine_split<<<(M_*C_/4)/256, blk>>>(op, g, oh, ol);

    // (5) output projection (HMMA)
    out_gemm<<<dim3(D_/128, M_/128), blk>>>(oh, ol, woh, wol, bo, out);
}

// round 16
// speedup vs baseline: 1.0724x; 1.0008x over previous
#include <cuda_runtime.h>
#include <cuda_bf16.h>
#include <cstdint>

#define B_ 16
#define T_ 4096
#define D_ 1024
#define C_ 128
#define M_ (B_*T_)        // 65536 tokens
#define GROUPS 8          // row-groups (16 rows each; 2 rows per warp)
#define LCH 4             // chunk length inside recurrence
#define NCH (T_/LCH)      // 1024 chunks per sequence

typedef __nv_bfloat16 bf16;

// ---------------- scratch (static device globals; no allocation) -------------
__device__ float g_q[(size_t)M_*C_];
__device__ float g_k[(size_t)M_*C_];
__device__ float g_v[(size_t)M_*C_];
__device__ float g_g[(size_t)M_*C_];
__device__ float g_qT[(size_t)M_*C_];   // [B][C][T]
__device__ float g_vT[(size_t)M_*C_];   // [B][C][T]
__device__ float g_a[M_];
__device__ float g_b[M_];
__device__ float g_opart[(size_t)GROUPS*M_*C_];
__device__ float g_gram[(size_t)B_*NCH*8];

__device__ bf16 g_xh[(size_t)M_*D_];
__device__ bf16 g_xl[(size_t)M_*D_];
__device__ bf16 g_oh[(size_t)M_*C_];
__device__ bf16 g_ol[(size_t)M_*C_];
__device__ bf16 g_wqh[C_*D_], g_wql[C_*D_];
__device__ bf16 g_wkh[C_*D_], g_wkl[C_*D_];
__device__ bf16 g_wvh[C_*D_], g_wvl[C_*D_];
__device__ bf16 g_wgh[C_*D_], g_wgl[C_*D_];
__device__ bf16 g_woh[D_*C_], g_wol[D_*C_];

__device__ __forceinline__ float sigmoidf_(float x) { return 1.0f / (1.0f + expf(-x)); }

// =============================================================================
// fused_prep: blocks [0, M_/8)            -> alpha/beta + x hi/lo split
//             blocks [M_/8, M_/8 + 640)   -> weight hi/lo splits (5 matrices)
// =============================================================================
__global__ __launch_bounds__(256) void fused_prep(
    const float* __restrict__ x,
    const float* __restrict__ Wa, const float* __restrict__ ba,
    const float* __restrict__ Wb, const float* __restrict__ bb,
    float* __restrict__ a_out, float* __restrict__ b_out,
    bf16* __restrict__ xh, bf16* __restrict__ xl,
    const float* Wq, const float* Wk, const float* Wv, const float* Wg, const float* Wo,
    bf16* wqh, bf16* wql, bf16* wkh, bf16* wkl, bf16* wvh, bf16* wvl,
    bf16* wgh, bf16* wgl, bf16* woh, bf16* wol)
{
    const int tid = threadIdx.x;
    constexpr int NAB = M_/8;

    if (blockIdx.x >= NAB) {
        const int widx = blockIdx.x - NAB;
        const int mat  = widx >> 7;
        const float* in; bf16 *hi, *lo;
        if      (mat == 0) { in = Wq; hi = wqh; lo = wql; }
        else if (mat == 1) { in = Wk; hi = wkh; lo = wkl; }
        else if (mat == 2) { in = Wv; hi = wvh; lo = wvl; }
        else if (mat == 3) { in = Wg; hi = wgh; lo = wgl; }
        else               { in = Wo; hi = woh; lo = wol; }
        const int i = (widx & 127) * 256 + tid;
        float4 xv = *(const float4*)(in + (size_t)i * 4);
        bf16 h0 = __float2bfloat16_rn(xv.x);
        bf16 h1 = __float2bfloat16_rn(xv.y);
        bf16 h2 = __float2bfloat16_rn(xv.z);
        bf16 h3 = __float2bfloat16_rn(xv.w);
        bf16 l0 = __float2bfloat16_rn(xv.x - __bfloat162float(h0));
        bf16 l1 = __float2bfloat16_rn(xv.y - __bfloat162float(h1));
        bf16 l2 = __float2bfloat16_rn(xv.z - __bfloat162float(h2));
        bf16 l3 = __float2bfloat16_rn(xv.w - __bfloat162float(h3));
        __nv_bfloat162* H = (__nv_bfloat162*)(hi + (size_t)i * 4);
        __nv_bfloat162* L = (__nv_bfloat162*)(lo + (size_t)i * 4);
        H[0] = __nv_bfloat162(h0, h1); H[1] = __nv_bfloat162(h2, h3);
        L[0] = __nv_bfloat162(l0, l1); L[1] = __nv_bfloat162(l2, l3);
        return;
    }

    __shared__ __align__(16) float sWa[D_];
    __shared__ __align__(16) float sWb[D_];
    for (int i = tid; i < D_; i += 256) { sWa[i] = Wa[i]; sWb[i] = Wb[i]; }
    __syncthreads();

    const int warp = tid >> 5, lane = tid & 31;
    const int tok  = blockIdx.x * 8 + warp;
    const size_t base = (size_t)tok * D_;
    const float* xr = x + base;

    float da = 0.0f, db = 0.0f;
#pragma unroll
    for (int j = 0; j < 8; ++j) {
        const int off = j*128 + lane*4;
        float4 xv = *(const float4*)(xr  + off);
        float4 wa = *(const float4*)(sWa + off);
        float4 wb = *(const float4*)(sWb + off);
        da += xv.x*wa.x + xv.y*wa.y + xv.z*wa.z + xv.w*wa.w;
        db += xv.x*wb.x + xv.y*wb.y + xv.z*wb.z + xv.w*wb.w;

        bf16 h0 = __float2bfloat16_rn(xv.x);
        bf16 h1 = __float2bfloat16_rn(xv.y);
        bf16 h2 = __float2bfloat16_rn(xv.z);
        bf16 h3 = __float2bfloat16_rn(xv.w);
        bf16 l0 = __float2bfloat16_rn(xv.x - __bfloat162float(h0));
        bf16 l1 = __float2bfloat16_rn(xv.y - __bfloat162float(h1));
        bf16 l2 = __float2bfloat16_rn(xv.z - __bfloat162float(h2));
        bf16 l3 = __float2bfloat16_rn(xv.w - __bfloat162float(h3));
        __nv_bfloat162* H = (__nv_bfloat162*)(xh + base + off);
        __nv_bfloat162* L = (__nv_bfloat162*)(xl + base + off);
        H[0] = __nv_bfloat162(h0, h1); H[1] = __nv_bfloat162(h2, h3);
        L[0] = __nv_bfloat162(l0, l1); L[1] = __nv_bfloat162(l2, l3);
    }
#pragma unroll
    for (int off = 16; off > 0; off >>= 1) {
        da += __shfl_xor_sync(0xffffffffu, da, off);
        db += __shfl_xor_sync(0xffffffffu, db, off);
    }
    if (lane == 0) {
        a_out[tok] = sigmoidf_(da + ba[0]);
        b_out[tok] = sigmoidf_(db + bb[0]);
    }
}

// =============================================================================
// Tensor-core NT GEMM core (HMMA mma.sync).
// =============================================================================
__device__ __forceinline__ void ldsm4(uint32_t& r0, uint32_t& r1,
                                      uint32_t& r2, uint32_t& r3, uint32_t a)
{
    asm volatile("ldmatrix.sync.aligned.m8n8.x4.shared.b16 {%0,%1,%2,%3}, [%4];"
                 : "=r"(r0), "=r"(r1), "=r"(r2), "=r"(r3) : "r"(a));
}

__device__ __forceinline__ void mma16816(float c[4], const uint32_t a[4], const uint32_t b[2])
{
    asm volatile("mma.sync.aligned.m16n8k16.row.col.f32.bf16.bf16.f32 "
                 "{%0,%1,%2,%3}, {%4,%5,%6,%7}, {%8,%9}, {%0,%1,%2,%3};"
                 : "+f"(c[0]), "+f"(c[1]), "+f"(c[2]), "+f"(c[3])
                 : "r"(a[0]), "r"(a[1]), "r"(a[2]), "r"(a[3]), "r"(b[0]), "r"(b[1]));
}

template<int KDIM>
__device__ __forceinline__ void mma_loop(const bf16* __restrict__ A0,
                                         const bf16* __restrict__ A1,
                                         const bf16* __restrict__ A2,
                                         const bf16* __restrict__ B0,
                                         const bf16* __restrict__ B1,
                                         const bf16* __restrict__ B2,
                                         int m0, uint4* sA, uint4* sB,
                                         float acc[4][4][4])
{
    constexpr int KIT = KDIM / 32;
    constexpr int TOT = 3 * KIT;
    const int tid  = threadIdx.x;
    const int lane = tid & 31, warp = tid >> 5;
    const int wm = warp & 1, wn = warp >> 1;

    const int r0_ = tid >> 2,        u_ = tid & 3;
    const int r1_ = 64 + (tid >> 2);
    const int st0 = r0_ * 4 + (u_ ^ ((r0_ >> 1) & 3));
    const int st1 = r1_ * 4 + (u_ ^ ((r1_ >> 1) & 3));

    const uint32_t saB = (uint32_t)__cvta_generic_to_shared(sA);
    const uint32_t sbB = (uint32_t)__cvta_generic_to_shared(sB);

    uint4 ra0, ra1, rb0, rb1;
    {
        ra0 = *(const uint4*)(A0 + (size_t)(m0 + r0_) * KDIM + u_ * 8);
        ra1 = *(const uint4*)(A0 + (size_t)(m0 + r1_) * KDIM + u_ * 8);
        rb0 = *(const uint4*)(B0 + (size_t)r0_ * KDIM + u_ * 8);
        rb1 = *(const uint4*)(B0 + (size_t)r1_ * KDIM + u_ * 8);
    }

#pragma unroll 1
    for (int it = 0; it < TOT; ++it) {
        const int buf = it & 1;
        sA[buf * 512 + st0] = ra0; sA[buf * 512 + st1] = ra1;
        sB[buf * 512 + st0] = rb0; sB[buf * 512 + st1] = rb1;
        __syncthreads();

        if (it + 1 < TOT) {
            const int nit = it + 1;
            const int p = nit / KIT;
            const int kk = (nit - p * KIT) * 32;
            const bf16* Ap = (p == 0) ? A0 : (p == 1) ? A1 : A2;
            const bf16* Bp = (p == 0) ? B0 : (p == 1) ? B1 : B2;
            ra0 = *(const uint4*)(Ap + (size_t)(m0 + r0_) * KDIM + kk + u_ * 8);
            ra1 = *(const uint4*)(Ap + (size_t)(m0 + r1_) * KDIM + kk + u_ * 8);
            rb0 = *(const uint4*)(Bp + (size_t)r0_ * KDIM + kk + u_ * 8);
            rb1 = *(const uint4*)(Bp + (size_t)r1_ * KDIM + kk + u_ * 8);
        }

        const uint32_t aBase = saB + buf * 8192;
        const uint32_t bBase = sbB + buf * 8192;
#pragma unroll
        for (int ks = 0; ks < 2; ++ks) {
            uint32_t af[4][4], bfr[4][2];
#pragma unroll
            for (int mt = 0; mt < 4; ++mt) {
                const int row = wm * 64 + mt * 16 + (lane & 15);
                const int u = ks * 2 + (lane >> 4);
                ldsm4(af[mt][0], af[mt][1], af[mt][2], af[mt][3],
                      aBase + (uint32_t)((row * 4 + (u ^ ((row >> 1) & 3))) * 16));
            }
#pragma unroll
            for (int j = 0; j < 2; ++j) {
                const int gq = lane >> 3;
                const int n = wn * 32 + j * 16 + ((gq >> 1) << 3) + (lane & 7);
                const int u = ks * 2 + (gq & 1);
                uint32_t t0, t1, t2, t3;
                ldsm4(t0, t1, t2, t3,
                      bBase + (uint32_t)((n * 4 + (u ^ ((n >> 1) & 3))) * 16));
                bfr[j*2][0] = t0; bfr[j*2][1] = t1;
                bfr[j*2+1][0] = t2; bfr[j*2+1][1] = t3;
            }
#pragma unroll
            for (int mt = 0; mt < 4; ++mt)
#pragma unroll
                for (int nt = 0; nt < 4; ++nt)
                    mma16816(acc[mt][nt], af[mt], bfr[nt]);
        }
    }
}

// =============================================================================
// Fused 4-projection GEMM (HMMA).
// =============================================================================
__global__ __launch_bounds__(256, 2) void proj_gemm(
    const bf16* __restrict__ xh, const bf16* __restrict__ xl,
    const bf16* wqh, const bf16* wql, const bf16* wkh, const bf16* wkl,
    const bf16* wvh, const bf16* wvl, const bf16* wgh, const bf16* wgl,
    const float* bq, const float* bk, const float* bv, const float* bg,
    float* outq, float* outk, float* outv, float* outg)
{
    __shared__ uint4 sA[1024];
    __shared__ uint4 sB[1024];
    __shared__ float snorm[4][128];

    const int proj = blockIdx.x;
    const int m0 = blockIdx.y * 128;
    const bf16 *Bh, *Bl; const float* bias; float* C;
    if      (proj == 0) { Bh = wqh; Bl = wql; bias = bq; C = outq; }
    else if (proj == 1) { Bh = wkh; Bl = wkl; bias = bk; C = outk; }
    else if (proj == 2) { Bh = wvh; Bl = wvl; bias = bv; C = outv; }
    else                { Bh = wgh; Bl = wgl; bias = bg; C = outg; }

    float acc[4][4][4];
#pragma unroll
    for (int mt = 0; mt < 4; ++mt)
#pragma unroll
        for (int nt = 0; nt < 4; ++nt)
#pragma unroll
            for (int c = 0; c < 4; ++c) acc[mt][nt][c] = 0.0f;

    mma_loop<D_>(xh, xh, xl, Bh, Bl, Bh, m0, sA, sB, acc);

    const int lane = threadIdx.x & 31, warp = threadIdx.x >> 5;
    const int wm = warp & 1, wn = warp >> 1;

#pragma unroll
    for (int nt = 0; nt < 4; ++nt) {
        const int col = wn * 32 + nt * 8 + (lane & 3) * 2;
        const float b0 = bias[col], b1 = bias[col + 1];
#pragma unroll
        for (int mt = 0; mt < 4; ++mt) {
            acc[mt][nt][0] += b0; acc[mt][nt][1] += b1;
            acc[mt][nt][2] += b0; acc[mt][nt][3] += b1;
        }
    }

    if (proj == 3) {
#pragma unroll
        for (int mt = 0; mt < 4; ++mt)
#pragma unroll
            for (int nt = 0; nt < 4; ++nt)
#pragma unroll
                for (int c = 0; c < 4; ++c)
                    acc[mt][nt][c] = sigmoidf_(acc[mt][nt][c]);
    }

    if (proj == 1) {
#pragma unroll
        for (int mt = 0; mt < 4; ++mt)
#pragma unroll
            for (int h = 0; h < 2; ++h) {
                float ss = 0.0f;
#pragma unroll
                for (int nt = 0; nt < 4; ++nt) {
                    ss += acc[mt][nt][2*h] * acc[mt][nt][2*h];
                    ss += acc[mt][nt][2*h+1] * acc[mt][nt][2*h+1];
                }
                ss += __shfl_xor_sync(0xffffffffu, ss, 1);
                ss += __shfl_xor_sync(0xffffffffu, ss, 2);
                if ((lane & 3) == 0)
                    snorm[wn][wm*64 + mt*16 + h*8 + (lane >> 2)] = ss;
            }
        __syncthreads();
#pragma unroll
        for (int mt = 0; mt < 4; ++mt)
#pragma unroll
            for (int h = 0; h < 2; ++h) {
                const int row = wm*64 + mt*16 + h*8 + (lane >> 2);
                const float s = snorm[0][row] + snorm[1][row] + snorm[2][row] + snorm[3][row];
                const float inv = 1.0f / fmaxf(sqrtf(s), 1e-12f);
#pragma unroll
                for (int nt = 0; nt < 4; ++nt) {
                    acc[mt][nt][2*h]   *= inv;
                    acc[mt][nt][2*h+1] *= inv;
                }
            }
    }

#pragma unroll
    for (int mt = 0; mt < 4; ++mt) {
        const int r = m0 + wm*64 + mt*16 + (lane >> 2);
#pragma unroll
        for (int nt = 0; nt < 4; ++nt) {
            const int col = wn*32 + nt*8 + (lane & 3)*2;
            *(float2*)(C + (size_t)r * C_ + col)       = make_float2(acc[mt][nt][0], acc[mt][nt][1]);
            *(float2*)(C + (size_t)(r+8) * C_ + col)   = make_float2(acc[mt][nt][2], acc[mt][nt][3]);
        }
    }
}

// =============================================================================
// Output GEMM (HMMA).
// =============================================================================
__global__ __launch_bounds__(256, 2) void out_gemm(
    const bf16* __restrict__ oh, const bf16* __restrict__ ol,
    const bf16* __restrict__ woh, const bf16* __restrict__ wol,
    const float* __restrict__ bo, float* __restrict__ out)
{
    __shared__ uint4 sA[1024];
    __shared__ uint4 sB[1024];

    const int n0 = blockIdx.x * 128;
    const int m0 = blockIdx.y * 128;
    const bf16* Bh = woh + (size_t)n0 * C_;
    const bf16* Bl = wol + (size_t)n0 * C_;

    float acc[4][4][4];
#pragma unroll
    for (int mt = 0; mt < 4; ++mt)
#pragma unroll
        for (int nt = 0; nt < 4; ++nt)
#pragma unroll
            for (int c = 0; c < 4; ++c) acc[mt][nt][c] = 0.0f;

    mma_loop<C_>(oh, oh, ol, Bh, Bl, Bh, m0, sA, sB, acc);

    const int lane = threadIdx.x & 31, warp = threadIdx.x >> 5;
    const int wm = warp & 1, wn = warp >> 1;

#pragma unroll
    for (int mt = 0; mt < 4; ++mt) {
        const int r = m0 + wm*64 + mt*16 + (lane >> 2);
#pragma unroll
        for (int nt = 0; nt < 4; ++nt) {
            const int col = n0 + wn*32 + nt*8 + (lane & 3)*2;
            const float b0 = bo[col], b1 = bo[col + 1];
            *(float2*)(out + (size_t)r * D_ + col)
                = make_float2(acc[mt][nt][0] + b0, acc[mt][nt][1] + b1);
            *(float2*)(out + (size_t)(r+8) * D_ + col)
                = make_float2(acc[mt][nt][2] + b0, acc[mt][nt][3] + b1);
        }
    }
}

// =============================================================================
// prep2: blocks [0, 2048)          -> chunk Gram precompute (1 warp per chunk)
//        blocks [2048, 2048+16384) -> q/v transpose to [B][C][T]
// =============================================================================
__global__ __launch_bounds__(256) void prep2(const float* __restrict__ k,
                                             const float* __restrict__ q,
                                             const float* __restrict__ v,
                                             float* __restrict__ gram,
                                             float* __restrict__ qT,
                                             float* __restrict__ vT)
{
    const int tid = threadIdx.x;

    if (blockIdx.x < 2048) {
        const int warp = tid >> 5, lane = tid & 31;
        const int cid = blockIdx.x * 8 + warp;
        const int bb = cid >> 10, tc = cid & 1023;
        const float* kg = k + ((size_t)bb * T_ + (size_t)tc * LCH) * C_ + lane * 4;

        float4 k0 = *(const float4*)(kg + 0*C_);
        float4 k1 = *(const float4*)(kg + 1*C_);
        float4 k2 = *(const float4*)(kg + 2*C_);
        float4 k3 = *(const float4*)(kg + 3*C_);

        float G01 = k0.x*k1.x + k0.y*k1.y + k0.z*k1.z + k0.w*k1.w;
        float G02 = k0.x*k2.x + k0.y*k2.y + k0.z*k2.z + k0.w*k2.w;
        float G03 = k0.x*k3.x + k0.y*k3.y + k0.z*k3.z + k0.w*k3.w;
        float G12 = k1.x*k2.x + k1.y*k2.y + k1.z*k2.z + k1.w*k2.w;
        float G13 = k1.x*k3.x + k1.y*k3.y + k1.z*k3.z + k1.w*k3.w;
        float G23 = k2.x*k3.x + k2.y*k3.y + k2.z*k3.z + k2.w*k3.w;

#pragma unroll
        for (int off = 16; off > 0; off >>= 1) {
            G01 += __shfl_xor_sync(0xffffffffu, G01, off);
            G02 += __shfl_xor_sync(0xffffffffu, G02, off);
            G03 += __shfl_xor_sync(0xffffffffu, G03, off);
            G12 += __shfl_xor_sync(0xffffffffu, G12, off);
            G13 += __shfl_xor_sync(0xffffffffu, G13, off);
            G23 += __shfl_xor_sync(0xffffffffu, G23, off);
        }
        if (lane == 0) {
            float* gp = gram + (size_t)cid * 8;
            *(float4*)(gp)     = make_float4(G01, G02, G03, G12);
            *(float4*)(gp + 4) = make_float4(G13, G23, 0.0f, 0.0f);
        }
        return;
    }

    __shared__ float ts[32][33];
    const int tt = blockIdx.x - 2048;
    const int tensor = tt >> 13;
    const int rem = tt & 8191;
    const int bb = rem >> 9;
    const int tile = rem & 511;
    const int ct = tile >> 7;
    const int tk = tile & 127;

    const float* src = tensor ? v : q;
    float* dst = tensor ? vT : qT;
    const size_t sbase = (size_t)bb * T_ * C_;

    const int ty = tid >> 5, lane = tid & 31;
#pragma unroll
    for (int r = 0; r < 4; ++r) {
        const int row = tk*32 + ty + r*8;
        ts[ty + r*8][lane] = src[sbase + (size_t)row * C_ + ct*32 + lane];
    }
    __syncthreads();
#pragma unroll
    for (int r = 0; r < 4; ++r) {
        const int c = ct*32 + ty + r*8;
        dst[sbase + (size_t)c * T_ + tk*32 + lane] = ts[lane][ty + r*8];
    }
}

// =============================================================================
// Chunked (L=4) gated delta-rule recurrence, GROUPS=8, TWO ROWS PER WARP.
// Grid (8, 16) = 128 CTAs, 1/SM. Warp w owns rows i0 = g*16+2w, i1 = i0+1;
// lane owns 4 cols of each row. po = q0*S0 + q1*S1 summed in registers ->
// per-warp k/STS/LDS traffic amortized over 2 rows (total L1 traffic halved).
// =============================================================================
struct ChunkRegs {
    float k[LCH][4];
    float q0[LCH], q1[LCH], v0[LCH], v1[LCH], a[LCH], b[LCH];
    float G[6];
};

__device__ __forceinline__ float red32(float x) {
    x += __shfl_xor_sync(0xffffffffu, x, 1);
    x += __shfl_xor_sync(0xffffffffu, x, 2);
    x += __shfl_xor_sync(0xffffffffu, x, 4);
    x += __shfl_xor_sync(0xffffffffu, x, 8);
    x += __shfl_xor_sync(0xffffffffu, x, 16);
    return x;
}

__device__ __forceinline__ void load_chunk(int tcN,
                                           const float* __restrict__ kg,
                                           const float* __restrict__ qT0,
                                           const float* __restrict__ qT1,
                                           const float* __restrict__ vT0,
                                           const float* __restrict__ vT1,
                                           const float* __restrict__ ag,
                                           const float* __restrict__ bg,
                                           const float* __restrict__ gramb,
                                           int jb, ChunkRegs& R)
{
#pragma unroll
    for (int t4 = 0; t4 < LCH; ++t4) {
        const size_t off = ((size_t)tcN*LCH + t4) * C_;
        float4 kx = *(const float4*)(kg + off + jb);
        R.k[t4][0]=kx.x; R.k[t4][1]=kx.y; R.k[t4][2]=kx.z; R.k[t4][3]=kx.w;
    }
    float4 q4 = *(const float4*)(qT0 + tcN*LCH);
    R.q0[0]=q4.x; R.q0[1]=q4.y; R.q0[2]=q4.z; R.q0[3]=q4.w;
    q4 = *(const float4*)(qT1 + tcN*LCH);
    R.q1[0]=q4.x; R.q1[1]=q4.y; R.q1[2]=q4.z; R.q1[3]=q4.w;
    float4 v4 = *(const float4*)(vT0 + tcN*LCH);
    R.v0[0]=v4.x; R.v0[1]=v4.y; R.v0[2]=v4.z; R.v0[3]=v4.w;
    v4 = *(const float4*)(vT1 + tcN*LCH);
    R.v1[0]=v4.x; R.v1[1]=v4.y; R.v1[2]=v4.z; R.v1[3]=v4.w;
    float4 a4 = *(const float4*)(ag + tcN*LCH);
    float4 b4 = *(const float4*)(bg + tcN*LCH);
    R.a[0]=a4.x; R.a[1]=a4.y; R.a[2]=a4.z; R.a[3]=a4.w;
    R.b[0]=b4.x; R.b[1]=b4.y; R.b[2]=b4.z; R.b[3]=b4.w;
    float4 ga = *(const float4*)(gramb + (size_t)tcN * 8);
    float4 gb = *(const float4*)(gramb + (size_t)tcN * 8 + 4);
    R.G[0]=ga.x; R.G[1]=ga.y; R.G[2]=ga.z; R.G[3]=ga.w;
    R.G[4]=gb.x; R.G[5]=gb.y;
}

// exact per-row scalar recursion (shared a,b,G; row-specific m,v)
__device__ __forceinline__ void row_recursion(const ChunkRegs& cur,
                                              const float m[LCH], const float* vv,
                                              float cc[LCH])
{
    const float a0=cur.a[0], a1=cur.a[1], a2=cur.a[2], a3=cur.a[3];
    const float G01=cur.G[0], G02=cur.G[1], G03=cur.G[2];
    const float G12=cur.G[3], G13=cur.G[4], G23=cur.G[5];
    const float u0 = m[0];
    cc[0] = cur.b[0] * (vv[0] - a0*u0);
    const float u1 = a0*m[1] + cc[0]*G01;
    cc[1] = cur.b[1] * (vv[1] - a1*u1);
    const float a01 = a0*a1;
    const float u2 = a01*m[2] + a1*cc[0]*G02 + cc[1]*G12;
    cc[2] = cur.b[2] * (vv[2] - a2*u2);
    const float u3 = a01*a2*m[3] + a1*a2*cc[0]*G03 + a2*cc[1]*G13 + cc[2]*G23;
    cc[3] = cur.b[3] * (vv[3] - a3*u3);
}

// osh layout: [buf(2)][step(8)][warp(8)][col(128)]
__device__ __forceinline__ void chunk_body(int tc, int buf, int cig, bool pf,
                                           float S0[4], float S1[4],
                                           ChunkRegs& cur, ChunkRegs& nxt,
                                           const float* __restrict__ kg,
                                           const float* __restrict__ qT0,
                                           const float* __restrict__ qT1,
                                           const float* __restrict__ vT0,
                                           const float* __restrict__ vT1,
                                           const float* __restrict__ ag,
                                           const float* __restrict__ bg,
                                           const float* __restrict__ gramb,
                                           int jb, int warp, int lane,
                                           float* __restrict__ osh)
{
    // --- phase 1: m partials vs chunk-start S for both rows ---
    float m0[LCH], m1[LCH];
#pragma unroll
    for (int t4 = 0; t4 < LCH; ++t4) {
        float s0 = 0.0f, s1 = 0.0f;
#pragma unroll
        for (int jj = 0; jj < 4; ++jj) {
            s0 += S0[jj] * cur.k[t4][jj];
            s1 += S1[jj] * cur.k[t4][jj];
        }
        m0[t4] = s0; m1[t4] = s1;
    }

    if (pf) load_chunk(tc + 1, kg, qT0, qT1, vT0, vT1, ag, bg, gramb, jb, nxt);

    // --- 8 independent full-warp reductions ---
    m0[0]=red32(m0[0]); m0[1]=red32(m0[1]); m0[2]=red32(m0[2]); m0[3]=red32(m0[3]);
    m1[0]=red32(m1[0]); m1[1]=red32(m1[1]); m1[2]=red32(m1[2]); m1[3]=red32(m1[3]);

    // --- phase 2: exact scalar recursion per row ---
    float cc0[LCH], cc1[LCH];
    row_recursion(cur, m0, cur.v0, cc0);
    row_recursion(cur, m1, cur.v1, cc1);

    // --- phase 3: per-step register updates + register-summed o partials ---
#pragma unroll
    for (int t4 = 0; t4 < LCH; ++t4) {
        float po[4];
#pragma unroll
        for (int jj = 0; jj < 4; ++jj) {
            S0[jj] = cur.a[t4] * S0[jj] + cc0[t4] * cur.k[t4][jj];
            S1[jj] = cur.a[t4] * S1[jj] + cc1[t4] * cur.k[t4][jj];
            po[jj] = cur.q0[t4] * S0[jj] + cur.q1[t4] * S1[jj];
        }
        const int step = cig * LCH + t4;
        *(float4*)&osh[(((size_t)buf*8 + step)*8 + warp)*C_ + lane*4]
            = make_float4(po[0], po[1], po[2], po[3]);
    }
}

__global__ __launch_bounds__(256) void recurrence4(const float* __restrict__ qT,
                                                   const float* __restrict__ k,
                                                   const float* __restrict__ vT,
                                                   const float* __restrict__ al,
                                                   const float* __restrict__ be,
                                                   const float* __restrict__ gram,
                                                   float* __restrict__ opart)
{
    extern __shared__ float osh[];   // [2][8][8][128] = 64 KB

    const int g   = blockIdx.x;   // 0..7
    const int bb  = blockIdx.y;   // 0..15
    const int tid = threadIdx.x;
    const int warp = tid >> 5, lane = tid & 31;
    const int i0 = g * 16 + warp * 2;
    const int i1 = i0 + 1;
    const int jb = lane * 4;

    const size_t bbase = (size_t)bb * T_ * C_;
    const size_t sbase = (size_t)bb * T_;
    const float* kg  = k + bbase;
    const float* qT0 = qT + bbase + (size_t)i0 * T_;
    const float* qT1 = qT + bbase + (size_t)i1 * T_;
    const float* vT0 = vT + bbase + (size_t)i0 * T_;
    const float* vT1 = vT + bbase + (size_t)i1 * T_;
    const float* ag = al + sbase;
    const float* bg = be + sbase;
    const float* gramb = gram + (size_t)bb * NCH * 8;
    float* op = opart + (size_t)g * M_ * C_ + bbase;

    float S0[4], S1[4];
#pragma unroll
    for (int jj = 0; jj < 4; ++jj) { S0[jj] = 0.0f; S1[jj] = 0.0f; }

    ChunkRegs RA, RB;
    load_chunk(0, kg, qT0, qT1, vT0, vT1, ag, bg, gramb, jb, RA);

    const int fst = tid >> 5;            // flush step 0..7
    const int fc4 = (tid & 31) * 4;      // flush col group

#pragma unroll 1
    for (int tc = 0; tc < NCH; tc += 2) {
        const int buf = (tc >> 1) & 1;
        chunk_body(tc,   buf, 0, true,          S0, S1, RA, RB, kg, qT0, qT1, vT0, vT1, ag, bg, gramb, jb, warp, lane, osh);
        chunk_body(tc+1, buf, 1, (tc+2) < NCH,  S0, S1, RB, RA, kg, qT0, qT1, vT0, vT1, ag, bg, gramb, jb, warp, lane, osh);
        __syncthreads();   // one barrier per 2 chunks

        // flush: 8 steps x 128 cols, 256 threads -> 1 float4 slot each
        const float* base = &osh[((size_t)buf*8 + fst)*8*C_];
        float4 acc = *(const float4*)(base + fc4);
#pragma unroll
        for (int w = 1; w < 8; ++w) {
            const float4 p = *(const float4*)(base + w*C_ + fc4);
            acc.x += p.x; acc.y += p.y; acc.z += p.z; acc.w += p.w;
        }
        *(float4*)(op + ((size_t)tc*LCH + fst) * C_ + fc4) = acc;
    }
}

// =============================================================================
// combine: o = (sum over groups of opart) * gate -> bf16 hi/lo split
// =============================================================================
__global__ __launch_bounds__(256) void combine_split(const float* __restrict__ opart,
                                                     const float* __restrict__ gate,
                                                     bf16* __restrict__ oh,
                                                     bf16* __restrict__ ol)
{
    const size_t idx = ((size_t)blockIdx.x * 256 + threadIdx.x) * 4;
    float4 s = make_float4(0.f, 0.f, 0.f, 0.f);
#pragma unroll
    for (int g = 0; g < GROUPS; ++g) {
        float4 p = *(const float4*)(opart + (size_t)g * M_ * C_ + idx);
        s.x += p.x; s.y += p.y; s.z += p.z; s.w += p.w;
    }
    float4 gt = *(const float4*)(gate + idx);
    s.x *= gt.x; s.y *= gt.y; s.z *= gt.z; s.w *= gt.w;

    bf16 h0 = __float2bfloat16_rn(s.x);
    bf16 h1 = __float2bfloat16_rn(s.y);
    bf16 h2 = __float2bfloat16_rn(s.z);
    bf16 h3 = __float2bfloat16_rn(s.w);
    bf16 l0 = __float2bfloat16_rn(s.x - __bfloat162float(h0));
    bf16 l1 = __float2bfloat16_rn(s.y - __bfloat162float(h1));
    bf16 l2 = __float2bfloat16_rn(s.z - __bfloat162float(h2));
    bf16 l3 = __float2bfloat16_rn(s.w - __bfloat162float(h3));
    __nv_bfloat162* H = (__nv_bfloat162*)(oh + idx);
    __nv_bfloat162* L = (__nv_bfloat162*)(ol + idx);
    H[0] = __nv_bfloat162(h0, h1); H[1] = __nv_bfloat162(h2, h3);
    L[0] = __nv_bfloat162(l0, l1); L[1] = __nv_bfloat162(l2, l3);
}

// =============================================================================
extern "C" void kernel_launch(void* const* d_in, const int* in_sizes, int n_in,
                              void* d_out, int out_size)
{
    const float* x  = (const float*)d_in[0];
    const float* Wq = (const float*)d_in[1];
    const float* bq = (const float*)d_in[2];
    const float* Wk = (const float*)d_in[3];
    const float* bk = (const float*)d_in[4];
    const float* Wv = (const float*)d_in[5];
    const float* bv = (const float*)d_in[6];
    const float* Wa = (const float*)d_in[7];
    const float* ba = (const float*)d_in[8];
    const float* Wb = (const float*)d_in[9];
    const float* bb = (const float*)d_in[10];
    const float* Wg = (const float*)d_in[11];
    const float* bg = (const float*)d_in[12];
    const float* Wo = (const float*)d_in[13];
    const float* bo = (const float*)d_in[14];
    float* out = (float*)d_out;

    float *q, *k, *v, *g, *qT, *vT, *a, *b, *op, *gram;
    bf16 *xh, *xl, *oh, *ol;
    bf16 *wqh, *wql, *wkh, *wkl, *wvh, *wvl, *wgh, *wgl, *woh, *wol;
    cudaGetSymbolAddress((void**)&q,  g_q);
    cudaGetSymbolAddress((void**)&k,  g_k);
    cudaGetSymbolAddress((void**)&v,  g_v);
    cudaGetSymbolAddress((void**)&g,  g_g);
    cudaGetSymbolAddress((void**)&qT, g_qT);
    cudaGetSymbolAddress((void**)&vT, g_vT);
    cudaGetSymbolAddress((void**)&a,  g_a);
    cudaGetSymbolAddress((void**)&b,  g_b);
    cudaGetSymbolAddress((void**)&op, g_opart);
    cudaGetSymbolAddress((void**)&gram, g_gram);
    cudaGetSymbolAddress((void**)&xh, g_xh);
    cudaGetSymbolAddress((void**)&xl, g_xl);
    cudaGetSymbolAddress((void**)&oh, g_oh);
    cudaGetSymbolAddress((void**)&ol, g_ol);
    cudaGetSymbolAddress((void**)&wqh, g_wqh); cudaGetSymbolAddress((void**)&wql, g_wql);
    cudaGetSymbolAddress((void**)&wkh, g_wkh); cudaGetSymbolAddress((void**)&wkl, g_wkl);
    cudaGetSymbolAddress((void**)&wvh, g_wvh); cudaGetSymbolAddress((void**)&wvl, g_wvl);
    cudaGetSymbolAddress((void**)&wgh, g_wgh); cudaGetSymbolAddress((void**)&wgl, g_wgl);
    cudaGetSymbolAddress((void**)&woh, g_woh); cudaGetSymbolAddress((void**)&wol, g_wol);

    const dim3 blk(256);
    const int OSH = 2*8*8*C_*4;   // 64 KB dynamic smem for recurrence

    cudaFuncSetAttribute(recurrence4, cudaFuncAttributeMaxDynamicSharedMemorySize, OSH);

    // (0) fused prep: alpha/beta + x split + 5 weight splits
    fused_prep<<<M_/8 + 5*128, blk>>>(x, Wa, ba, Wb, bb, a, b, xh, xl,
                                      Wq, Wk, Wv, Wg, Wo,
                                      wqh, wql, wkh, wkl, wvh, wvl,
                                      wgh, wgl, woh, wol);

    // (1) fused 4-projection HMMA GEMM (k-norm + gate-sigmoid in epilogue)
    proj_gemm<<<dim3(4, M_/128), blk>>>(xh, xl,
                                        wqh, wql, wkh, wkl, wvh, wvl, wgh, wgl,
                                        bq, bk, bv, bg, q, k, v, g);

    // (2) gram + q/v transpose
    prep2<<<2048 + 16384, blk>>>(k, q, v, gram, qT, vT);

    // (3) chunked sequential recurrence (128 CTAs, 2 rows/warp)  <- profiled
    recurrence4<<<dim3(GROUPS, B_), blk, OSH>>>(qT, k, vT, a, b, gram, op);

    // (4) group-sum + gate -> bf16 split
    combine_split<<<(M_*C_/4)/256, blk>>>(op, g, oh, ol);

    // (5) output projection (HMMA)
    out_gemm<<<dim3(D_/128, M_/128), blk>>>(oh, ol, woh, wol, bo, out);
}